// round 5
// baseline (speedup 1.0000x reference)
#include <cuda_runtime.h>
#include <math_constants.h>

#define BB 2
#define LL 2048
#define NH 16
#define DD 64
#define SCALE 0.125f
#define NEGINF -1.0e9f

#define NTJ 64                   // number of j-tiles (2048/32)
#define NROWS (BB * NH * LL)     // 65536 softmax rows

// per-(row, j-tile) partial softmax stats, layout [jt][b][n][i]
__device__ float g_tm[NTJ * NROWS];
__device__ float g_tl[NTJ * NROWS];
// final stats, layout [b][i][n]
__device__ float g_m[BB * LL * NH];
__device__ float g_rl[BB * LL * NH];

// ---------------------------------------------------------------------------
// Kernel 1: masked scaled scores -> attn buffer [B][L_i][L_j][NH]
//           + per-tile softmax (max, sumexp) into g_tm/g_tl.
// CTA: 256 thr = 8 warps = 8 heads; tile 32i x 32j; z = b*2 + head-half.
// Lane: 4i x 8j micro-tile; float4 LDS with hoisted XOR swizzle.
// ---------------------------------------------------------------------------
__global__ __launch_bounds__(256, 2) void k_scores(
    const float* __restrict__ q, const float* __restrict__ k,
    const int* __restrict__ mask, float* __restrict__ attn)
{
    extern __shared__ float smem[];
    float* Qs = smem;           // [8 w][32 ii][32 d] swizzled
    float* Ks = smem + 8192;    // [8 w][32 jj][32 d] swizzled
    __shared__ int Msk[1024];   // [32 ii][32 jj]

    const int b  = blockIdx.z >> 1;
    const int nb = (blockIdx.z & 1) * 8;
    const int i0 = blockIdx.y * 32;
    const int j0 = blockIdx.x * 32;
    const int jt = blockIdx.x;
    const int tid  = threadIdx.x;
    const int w    = tid >> 5;        // local head
    const int n    = nb + w;          // global head
    const int lane = tid & 31;
    const int ii_g = lane & 7;  const int ii0 = ii_g * 4;  // 4 rows
    const int jj_g = lane >> 3; const int jj0 = jj_g * 8;  // 8 cols
    const int cq  = ii_g;             // Q swizzle const (all 4 rows)
    const int ck0 = jj_g * 2;         // K swizzle const rows v=0..3
    const int ck1 = jj_g * 2 + 1;     // K swizzle const rows v=4..7

    for (int idx = tid; idx < 1024; idx += 256)
        Msk[idx] = mask[((size_t)(b * LL + i0 + (idx >> 5))) * LL + j0 + (idx & 31)];

    float acc[4][8];
#pragma unroll
    for (int u = 0; u < 4; u++)
#pragma unroll
        for (int v = 0; v < 8; v++) acc[u][v] = 0.f;

#pragma unroll
    for (int dc = 0; dc < DD; dc += 32) {
        __syncthreads();
        // Q chunk: 2048 float4 (8 heads x 32 rows x 8 f4)
        for (int idx = tid; idx < 2048; idx += 256) {
            int d4 = idx & 7; int nn = (idx >> 3) & 7; int ii = idx >> 6;
            float4 val = *(const float4*)&q[
                (((size_t)(b * LL + i0 + ii)) * NH + nb + nn) * DD + dc + d4 * 4];
            *(float4*)&Qs[(nn * 32 + ii) * 32 + ((d4 ^ (ii >> 2)) << 2)] = val;
        }
        // K chunk
        for (int idx = tid; idx < 2048; idx += 256) {
            int d4 = idx & 7; int nn = (idx >> 3) & 7; int jj = idx >> 6;
            float4 val = *(const float4*)&k[
                (((size_t)(b * LL + j0 + jj)) * NH + nb + nn) * DD + dc + d4 * 4];
            *(float4*)&Ks[(nn * 32 + jj) * 32 + ((d4 ^ (jj >> 2)) << 2)] = val;
        }
        __syncthreads();

        const float* qb = Qs + (w * 32 + ii0) * 32;
        const float* kb = Ks + (w * 32 + jj0) * 32;
#pragma unroll
        for (int g = 0; g < 8; g++) {
            const float4* qp  = (const float4*)(qb + ((g ^ cq)  << 2));
            const float4* kp0 = (const float4*)(kb + ((g ^ ck0) << 2));
            const float4* kp1 = (const float4*)(kb + 128 + ((g ^ ck1) << 2));
            float4 qa[4], kv[8];
#pragma unroll
            for (int u = 0; u < 4; u++) qa[u] = qp[u * 8];
#pragma unroll
            for (int v = 0; v < 4; v++) kv[v] = kp0[v * 8];
#pragma unroll
            for (int v = 0; v < 4; v++) kv[4 + v] = kp1[v * 8];
#pragma unroll
            for (int u = 0; u < 4; u++)
#pragma unroll
                for (int v = 0; v < 8; v++) {
                    acc[u][v] += qa[u].x * kv[v].x;
                    acc[u][v] += qa[u].y * kv[v].y;
                    acc[u][v] += qa[u].z * kv[v].z;
                    acc[u][v] += qa[u].w * kv[v].w;
                }
        }
    }

    // scale + mask + per-tile stats (reduce over 32 j within tile)
    float mrow[4], lrow[4];
#pragma unroll
    for (int u = 0; u < 4; u++) {
        float mm = -CUDART_INF_F;
#pragma unroll
        for (int v = 0; v < 8; v++) {
            float s = acc[u][v] * SCALE;
            if (Msk[(ii0 + u) * 32 + jj0 + v] != 0) s = NEGINF;
            acc[u][v] = s;
            mm = fmaxf(mm, s);
        }
        mm = fmaxf(mm, __shfl_xor_sync(0xffffffffu, mm, 8));
        mm = fmaxf(mm, __shfl_xor_sync(0xffffffffu, mm, 16));
        float ll = 0.f;
#pragma unroll
        for (int v = 0; v < 8; v++) ll += __expf(acc[u][v] - mm);
        ll += __shfl_xor_sync(0xffffffffu, ll, 8);
        ll += __shfl_xor_sync(0xffffffffu, ll, 16);
        mrow[u] = mm; lrow[u] = ll;
    }
    if (jj_g == 0) {
#pragma unroll
        for (int u = 0; u < 4; u++) {
            size_t r = ((size_t)(b * NH + n)) * LL + i0 + ii0 + u;
            g_tm[(size_t)jt * NROWS + r] = mrow[u];
            g_tl[(size_t)jt * NROWS + r] = lrow[u];
        }
    }

    // stage in smem and store coalesced
    __syncthreads();
    float* Ss = smem;  // [32 ii][32 jj][pitch 9], 9216 floats
#pragma unroll
    for (int u = 0; u < 4; u++)
#pragma unroll
        for (int v = 0; v < 8; v++)
            Ss[((ii0 + u) * 32 + jj0 + v) * 9 + w] = acc[u][v];
    __syncthreads();

    for (int idx = tid; idx < 8192; idx += 256) {
        int nn = idx & 7; int jj = (idx >> 3) & 31; int ii = idx >> 8;
        attn[(((size_t)(b * LL + i0 + ii)) * LL + j0 + jj) * NH + nb + nn] =
            Ss[(ii * 32 + jj) * 9 + nn];
    }
}

// ---------------------------------------------------------------------------
// Kernel 2: combine tile stats -> g_m, g_rl. One thread per softmax row.
// ---------------------------------------------------------------------------
__global__ __launch_bounds__(256) void k_comb()
{
    const int r = blockIdx.x * 256 + threadIdx.x;   // [b][n][i]
    float M = -CUDART_INF_F, L = 0.f;
#pragma unroll 4
    for (int t = 0; t < NTJ; t++) {
        float m2 = g_tm[(size_t)t * NROWS + r];
        float l2 = g_tl[(size_t)t * NROWS + r];
        if (m2 > M) { L = L * __expf(M - m2) + l2; M = m2; }
        else        { L += l2 * __expf(m2 - M); }
    }
    const int i = r & (LL - 1);
    const int n = (r >> 11) & (NH - 1);
    const int b = r >> 15;
    g_m[((size_t)(b * LL + i)) * NH + n]  = M;
    g_rl[((size_t)(b * LL + i)) * NH + n] = 1.f / L;
}

// ---------------------------------------------------------------------------
// Kernel 3: normalize probs in place + context = P@V. (unchanged)
// ---------------------------------------------------------------------------
__global__ __launch_bounds__(512, 2) void k_pv(
    float* __restrict__ attn, const float* __restrict__ v,
    float* __restrict__ ctx)
{
    extern __shared__ float smem[];
    float* Ps = smem;             // [16 jj][16 n][20]
    float* Vs = Ps + 5120;        // [16 jj][16 n][64 d]
    float* Ms = Vs + 16384;       // [16 ii][16 n]
    float* Rs = Ms + 256;

    const int b  = blockIdx.y;
    const int i0 = blockIdx.x * 16;
    const int tid = threadIdx.x;

    if (tid < 256) {
        int ii = tid >> 4, nn = tid & 15;
        Ms[tid] = g_m[(size_t)(b * LL + i0 + ii) * NH + nn];
        Rs[tid] = g_rl[(size_t)(b * LL + i0 + ii) * NH + nn];
    }

    const int n  = tid >> 5;
    const int lane = tid & 31;
    const int dq = lane & 15;
    const int hs = lane >> 4;

    float4 acc[8];
#pragma unroll
    for (int r = 0; r < 8; r++) acc[r] = make_float4(0.f, 0.f, 0.f, 0.f);

    __syncthreads();

    for (int j0 = 0; j0 < LL; j0 += 16) {
        for (int idx = tid; idx < 4096; idx += 512) {
            int nn = idx & 15; int jj = (idx >> 4) & 15; int ii = idx >> 8;
            size_t g = (((size_t)(b * LL + i0 + ii)) * LL + j0 + jj) * NH + nn;
            float p = __expf(attn[g] - Ms[ii * 16 + nn]) * Rs[ii * 16 + nn];
            attn[g] = p;
            Ps[(jj * 16 + nn) * 20 + ii] = p;
        }
        for (int idx = tid; idx < 16384; idx += 512) {
            int d = idx & 63; int nn = (idx >> 6) & 15; int jj = idx >> 10;
            Vs[(jj * 16 + nn) * 64 + d] =
                v[(((size_t)(b * LL + j0 + jj)) * NH + nn) * DD + d];
        }
        __syncthreads();

#pragma unroll 4
        for (int jj = 0; jj < 16; jj++) {
            const float* pr = &Ps[(jj * 16 + n) * 20 + hs * 8];
            float4 p0 = *(const float4*)(pr);
            float4 p1 = *(const float4*)(pr + 4);
            float4 vv = *(const float4*)&Vs[(jj * 16 + n) * 64 + dq * 4];
            acc[0].x += p0.x * vv.x; acc[0].y += p0.x * vv.y; acc[0].z += p0.x * vv.z; acc[0].w += p0.x * vv.w;
            acc[1].x += p0.y * vv.x; acc[1].y += p0.y * vv.y; acc[1].z += p0.y * vv.z; acc[1].w += p0.y * vv.w;
            acc[2].x += p0.z * vv.x; acc[2].y += p0.z * vv.y; acc[2].z += p0.z * vv.z; acc[2].w += p0.z * vv.w;
            acc[3].x += p0.w * vv.x; acc[3].y += p0.w * vv.y; acc[3].z += p0.w * vv.z; acc[3].w += p0.w * vv.w;
            acc[4].x += p1.x * vv.x; acc[4].y += p1.x * vv.y; acc[4].z += p1.x * vv.z; acc[4].w += p1.x * vv.w;
            acc[5].x += p1.y * vv.x; acc[5].y += p1.y * vv.y; acc[5].z += p1.y * vv.z; acc[5].w += p1.y * vv.w;
            acc[6].x += p1.z * vv.x; acc[6].y += p1.z * vv.y; acc[6].z += p1.z * vv.z; acc[6].w += p1.z * vv.w;
            acc[7].x += p1.w * vv.x; acc[7].y += p1.w * vv.y; acc[7].z += p1.w * vv.z; acc[7].w += p1.w * vv.w;
        }
        __syncthreads();
    }

#pragma unroll
    for (int r = 0; r < 8; r++) {
        int ii = hs * 8 + r;
        size_t g = (((size_t)(b * LL + i0 + ii)) * NH + n) * DD + dq * 4;
        *(float4*)(ctx + g) = acc[r];
    }
}

// ---------------------------------------------------------------------------
extern "C" void kernel_launch(void* const* d_in, const int* in_sizes, int n_in,
                              void* d_out, int out_size)
{
    const float* q = (const float*)d_in[0];
    const float* k = (const float*)d_in[1];
    const float* v = (const float*)d_in[2];
    const int* mask = (const int*)d_in[3];

    float* ctx  = (float*)d_out;
    float* attn = (float*)d_out + (size_t)BB * LL * NH * DD;

    const int smem1 = 16384 * 4;                            // 64 KB
    const int smem3 = (5120 + 16384 + 256 + 256) * 4;       // ~88 KB
    cudaFuncSetAttribute(k_scores, cudaFuncAttributeMaxDynamicSharedMemorySize, smem1);
    cudaFuncSetAttribute(k_pv,     cudaFuncAttributeMaxDynamicSharedMemorySize, smem3);

    dim3 g1(LL / 32, LL / 32, BB * 2);
    k_scores<<<g1, 256, smem1>>>(q, k, mask, attn);

    k_comb<<<NROWS / 256, 256>>>();

    dim3 g3(LL / 16, BB);
    k_pv<<<g3, 512, smem3>>>(attn, v, ctx);
}

// round 7
// speedup vs baseline: 1.3374x; 1.3374x over previous
#include <cuda_runtime.h>
#include <cuda_bf16.h>
#include <math_constants.h>
#include <cstdint>

#define BB 2
#define LL 2048
#define NH 16
#define DD 64
#define SCALE 0.125f

#define TI 128
#define TJ 128
#define NTJ (LL / TJ)            // 16 j-tiles
#define NROWS (BB * NH * LL)     // 65536 softmax rows
#define PCH 72                   // smem pitch in bf16 (144B: 16B-offset rows -> conflict-free)

// scores scratch: u = exp(masked scaled score), layout [b][n][i][j]
__device__ float g_scores[(size_t)BB * NH * LL * LL];
// per-(row, j-tile) partial sums of u, layout [jt][b][n][i]
__device__ float g_tl[NTJ * NROWS];
// final per-row 1/sum, layout [b][i][n]
__device__ float g_c[BB * LL * NH];

// ---------------- portable tensor helpers (sm_80+) ----------------
__device__ __forceinline__ uint32_t smem_u32(const void* p) {
    uint32_t a;
    asm("{ .reg .u64 t; cvta.to.shared.u64 t, %1; cvt.u32.u64 %0, t; }" : "=r"(a) : "l"(p));
    return a;
}

__device__ __forceinline__ void ldmatrix_x4(uint32_t& r0, uint32_t& r1,
                                            uint32_t& r2, uint32_t& r3, uint32_t addr) {
    asm volatile("ldmatrix.sync.aligned.m8n8.x4.shared.b16 {%0,%1,%2,%3}, [%4];"
                 : "=r"(r0), "=r"(r1), "=r"(r2), "=r"(r3) : "r"(addr));
}

__device__ __forceinline__ void mma_bf16(float4& d, const uint32_t a[4],
                                         uint32_t b0, uint32_t b1) {
    asm volatile(
        "mma.sync.aligned.m16n8k16.row.col.f32.bf16.bf16.f32 "
        "{%0,%1,%2,%3},{%4,%5,%6,%7},{%8,%9},{%0,%1,%2,%3};"
        : "+f"(d.x), "+f"(d.y), "+f"(d.z), "+f"(d.w)
        : "r"(a[0]), "r"(a[1]), "r"(a[2]), "r"(a[3]), "r"(b0), "r"(b1));
}

// smem element offsets (bf16 units)
#define QHI_OFF 0
#define QLO_OFF (TI * PCH)
#define KHI_OFF (2 * TI * PCH)
#define KLO_OFF (2 * TI * PCH + TJ * PCH)
#define SMEM1_BYTES ((2 * TI * PCH + 2 * TJ * PCH) * 2)   // 73728 B

// ---------------------------------------------------------------------------
// Kernel 1: HMMA scores. CTA = (b,n) x 128i x 128j. 256 thr = 8 warps (4i x 2j).
// bf16x3: acc = Qhi*Khi + Qhi*Klo + Qlo*Khi (fp32).
// Epilogue: u = mask ? 0 : exp(acc*SCALE) -> g_scores; row partial sums -> g_tl.
// ---------------------------------------------------------------------------
__global__ __launch_bounds__(256, 2) void k_scores(
    const float* __restrict__ q, const float* __restrict__ k,
    const int* __restrict__ mask)
{
    extern __shared__ __nv_bfloat16 sb[];
    __shared__ float s_l[2][TI];

    const int b  = blockIdx.x >> 4;
    const int n  = blockIdx.x & 15;
    const int j0 = blockIdx.y * TJ;
    const int jt = blockIdx.y;
    const int i0 = blockIdx.z * TI;
    const int tid  = threadIdx.x;
    const int w    = tid >> 5;
    const int lane = tid & 31;
    const int wi = w >> 1;           // i row-group (0..3): rows wi*32..+31
    const int wj = w & 1;            // j half (0..1): cols wj*64..+63

    // ---- stage Q and K tiles, hi/lo bf16 split ----
    for (int idx = tid; idx < TI * 32; idx += 256) {
        int d2 = idx & 31, r = idx >> 5;
        float2 xq = *(const float2*)&q[(((size_t)(b * LL + i0 + r)) * NH + n) * DD + d2 * 2];
        float2 xk = *(const float2*)&k[(((size_t)(b * LL + j0 + r)) * NH + n) * DD + d2 * 2];
        __nv_bfloat16 qh0 = __float2bfloat16_rn(xq.x), qh1 = __float2bfloat16_rn(xq.y);
        __nv_bfloat16 kh0 = __float2bfloat16_rn(xk.x), kh1 = __float2bfloat16_rn(xk.y);
        __nv_bfloat16 ql0 = __float2bfloat16_rn(xq.x - __bfloat162float(qh0));
        __nv_bfloat16 ql1 = __float2bfloat16_rn(xq.y - __bfloat162float(qh1));
        __nv_bfloat16 kl0 = __float2bfloat16_rn(xk.x - __bfloat162float(kh0));
        __nv_bfloat16 kl1 = __float2bfloat16_rn(xk.y - __bfloat162float(kh1));
        int o = r * PCH + d2 * 2;
        *(__nv_bfloat162*)&sb[QHI_OFF + o] = __nv_bfloat162(qh0, qh1);
        *(__nv_bfloat162*)&sb[QLO_OFF + o] = __nv_bfloat162(ql0, ql1);
        *(__nv_bfloat162*)&sb[KHI_OFF + o] = __nv_bfloat162(kh0, kh1);
        *(__nv_bfloat162*)&sb[KLO_OFF + o] = __nv_bfloat162(kl0, kl1);
    }
    __syncthreads();

    float4 acc[2][8];
#pragma unroll
    for (int f = 0; f < 2; f++)
#pragma unroll
        for (int jf = 0; jf < 8; jf++) acc[f][jf] = make_float4(0.f, 0.f, 0.f, 0.f);

    // ldmatrix lane address components
    const int a_row = wi * 32 + (lane & 15);
    const int a_kof = (lane >> 4) << 3;
    const int b_row = wj * 64 + ((lane >> 4) << 3) + (lane & 7);
    const int b_kof = ((lane >> 3) & 1) << 3;

#pragma unroll
    for (int ks = 0; ks < 4; ks++) {
        const int k0 = ks * 16;
        uint32_t ah[2][4], al[2][4];
#pragma unroll
        for (int f = 0; f < 2; f++) {
            uint32_t aaddr = smem_u32(&sb[QHI_OFF + (a_row + f * 16) * PCH + k0 + a_kof]);
            ldmatrix_x4(ah[f][0], ah[f][1], ah[f][2], ah[f][3], aaddr);
            uint32_t laddr = smem_u32(&sb[QLO_OFF + (a_row + f * 16) * PCH + k0 + a_kof]);
            ldmatrix_x4(al[f][0], al[f][1], al[f][2], al[f][3], laddr);
        }
#pragma unroll
        for (int jp = 0; jp < 4; jp++) {
            uint32_t bh0, bh1, bh2, bh3, bl0, bl1, bl2, bl3;
            uint32_t bha = smem_u32(&sb[KHI_OFF + (b_row + jp * 16) * PCH + k0 + b_kof]);
            uint32_t bla = smem_u32(&sb[KLO_OFF + (b_row + jp * 16) * PCH + k0 + b_kof]);
            ldmatrix_x4(bh0, bh1, bh2, bh3, bha);
            ldmatrix_x4(bl0, bl1, bl2, bl3, bla);
#pragma unroll
            for (int f = 0; f < 2; f++) {
                mma_bf16(acc[f][jp * 2],     ah[f], bh0, bh1);
                mma_bf16(acc[f][jp * 2],     ah[f], bl0, bl1);
                mma_bf16(acc[f][jp * 2],     al[f], bh0, bh1);
                mma_bf16(acc[f][jp * 2 + 1], ah[f], bh2, bh3);
                mma_bf16(acc[f][jp * 2 + 1], ah[f], bl2, bl3);
                mma_bf16(acc[f][jp * 2 + 1], al[f], bh2, bh3);
            }
        }
    }

    // ---- epilogue: u = exp(s) (masked -> 0), store, row partial sums ----
    const int qr = lane >> 2, qc = (lane & 3) * 2;
    float ls[2][2] = {{0.f, 0.f}, {0.f, 0.f}};
#pragma unroll
    for (int f = 0; f < 2; f++) {
        const int r0 = i0 + wi * 32 + f * 16 + qr;      // global i, second row r0+8
        const size_t mrow0 = (size_t)(b * LL + r0) * LL;
        const size_t srow0 = ((size_t)(b * NH + n) * LL + r0) * LL;
#pragma unroll
        for (int jf = 0; jf < 8; jf++) {
            const int col = j0 + wj * 64 + jf * 8 + qc;
            float4 a = acc[f][jf];
            int2 m0 = *(const int2*)&mask[mrow0 + col];
            int2 m1 = *(const int2*)&mask[mrow0 + 8 * LL + col];
            float2 u0, u1;
            u0.x = m0.x ? 0.f : __expf(a.x * SCALE);
            u0.y = m0.y ? 0.f : __expf(a.y * SCALE);
            u1.x = m1.x ? 0.f : __expf(a.z * SCALE);
            u1.y = m1.y ? 0.f : __expf(a.w * SCALE);
            *(float2*)&g_scores[srow0 + col] = u0;
            *(float2*)&g_scores[srow0 + 8 * LL + col] = u1;
            ls[f][0] += u0.x + u0.y;
            ls[f][1] += u1.x + u1.y;
        }
    }
#pragma unroll
    for (int f = 0; f < 2; f++)
#pragma unroll
        for (int h = 0; h < 2; h++) {
            float v = ls[f][h];
            v += __shfl_xor_sync(0xffffffffu, v, 1);
            v += __shfl_xor_sync(0xffffffffu, v, 2);
            ls[f][h] = v;
        }
    if ((lane & 3) == 0) {
#pragma unroll
        for (int f = 0; f < 2; f++)
#pragma unroll
            for (int h = 0; h < 2; h++)
                s_l[wj][wi * 32 + f * 16 + h * 8 + qr] = ls[f][h];
    }
    __syncthreads();
    if (tid < TI) {
        float L = s_l[0][tid] + s_l[1][tid];
        g_tl[(size_t)jt * NROWS + (size_t)(b * NH + n) * LL + i0 + tid] = L;
    }
}

// ---------------------------------------------------------------------------
// Kernel 2: combine tile sums -> g_c = 1/L. One thread per softmax row.
// ---------------------------------------------------------------------------
__global__ __launch_bounds__(256) void k_comb()
{
    const int r = blockIdx.x * 256 + threadIdx.x;   // [b][n][i]
    float L = 0.f;
#pragma unroll
    for (int t = 0; t < NTJ; t++) L += g_tl[(size_t)t * NROWS + r];
    const int i = r & (LL - 1);
    const int n = (r >> 11) & (NH - 1);
    const int b = r >> 15;
    g_c[((size_t)(b * LL + i)) * NH + n] = 1.f / L;
}

// ---------------------------------------------------------------------------
// Kernel 3: p = u * c (no exp); write attn [b,i,j,n]; context = P@V.
// CTA per (b, i-tile 16). 512 threads.
// ---------------------------------------------------------------------------
__global__ __launch_bounds__(512, 2) void k_pv(
    float* __restrict__ attn, const float* __restrict__ v,
    float* __restrict__ ctx)
{
    extern __shared__ float smemf[];
    float* Ps = smemf;            // [16 jj][16 n][20]
    float* Vs = Ps + 5120;        // [16 jj][16 n][64 d]
    float* Cs = Vs + 16384;       // [16 ii][16 n]

    const int b  = blockIdx.y;
    const int i0 = blockIdx.x * 16;
    const int tid = threadIdx.x;

    if (tid < 256) {
        int ii = tid >> 4, nn = tid & 15;
        Cs[tid] = g_c[(size_t)(b * LL + i0 + ii) * NH + nn];
    }

    const int n  = tid >> 5;
    const int lane = tid & 31;
    const int dq = lane & 15;
    const int hs = lane >> 4;

    float4 acc[8];
#pragma unroll
    for (int r = 0; r < 8; r++) acc[r] = make_float4(0.f, 0.f, 0.f, 0.f);

    __syncthreads();

    for (int j0 = 0; j0 < LL; j0 += 16) {
        // read scratch coalesced (j fastest), scale, stage transposed
        for (int idx = tid; idx < 4096; idx += 512) {
            int jj = idx & 15; int nn = (idx >> 4) & 15; int ii = idx >> 8;
            float u = g_scores[((size_t)(b * NH + nn) * LL + i0 + ii) * LL + j0 + jj];
            Ps[(jj * 16 + nn) * 20 + ii] = u * Cs[ii * 16 + nn];
        }
        // stage V tile [16 jj][16 n][64 d]
        for (int idx = tid; idx < 16384; idx += 512) {
            int d = idx & 63; int nn = (idx >> 6) & 15; int jj = idx >> 10;
            Vs[(jj * 16 + nn) * 64 + d] =
                v[(((size_t)(b * LL + j0 + jj)) * NH + nn) * DD + d];
        }
        __syncthreads();

        // write final attention coalesced (n fastest)
        for (int idx = tid; idx < 4096; idx += 512) {
            int nn = idx & 15; int jj = (idx >> 4) & 15; int ii = idx >> 8;
            attn[(((size_t)(b * LL + i0 + ii)) * LL + j0 + jj) * NH + nn] =
                Ps[(jj * 16 + nn) * 20 + ii];
        }

#pragma unroll 4
        for (int jj = 0; jj < 16; jj++) {
            const float* pr = &Ps[(jj * 16 + n) * 20 + hs * 8];
            float4 p0 = *(const float4*)(pr);
            float4 p1 = *(const float4*)(pr + 4);
            float4 vv = *(const float4*)&Vs[(jj * 16 + n) * 64 + dq * 4];
            acc[0].x += p0.x * vv.x; acc[0].y += p0.x * vv.y; acc[0].z += p0.x * vv.z; acc[0].w += p0.x * vv.w;
            acc[1].x += p0.y * vv.x; acc[1].y += p0.y * vv.y; acc[1].z += p0.y * vv.z; acc[1].w += p0.y * vv.w;
            acc[2].x += p0.z * vv.x; acc[2].y += p0.z * vv.y; acc[2].z += p0.z * vv.z; acc[2].w += p0.z * vv.w;
            acc[3].x += p0.w * vv.x; acc[3].y += p0.w * vv.y; acc[3].z += p0.w * vv.z; acc[3].w += p0.w * vv.w;
            acc[4].x += p1.x * vv.x; acc[4].y += p1.x * vv.y; acc[4].z += p1.x * vv.z; acc[4].w += p1.x * vv.w;
            acc[5].x += p1.y * vv.x; acc[5].y += p1.y * vv.y; acc[5].z += p1.y * vv.z; acc[5].w += p1.y * vv.w;
            acc[6].x += p1.z * vv.x; acc[6].y += p1.z * vv.y; acc[6].z += p1.z * vv.z; acc[6].w += p1.z * vv.w;
            acc[7].x += p1.w * vv.x; acc[7].y += p1.w * vv.y; acc[7].z += p1.w * vv.z; acc[7].w += p1.w * vv.w;
        }
        __syncthreads();
    }

#pragma unroll
    for (int r = 0; r < 8; r++) {
        int ii = hs * 8 + r;
        size_t g = (((size_t)(b * LL + i0 + ii)) * NH + n) * DD + dq * 4;
        *(float4*)(ctx + g) = acc[r];
    }
}

// ---------------------------------------------------------------------------
extern "C" void kernel_launch(void* const* d_in, const int* in_sizes, int n_in,
                              void* d_out, int out_size)
{
    const float* q = (const float*)d_in[0];
    const float* k = (const float*)d_in[1];
    const float* v = (const float*)d_in[2];
    const int* mask = (const int*)d_in[3];

    float* ctx  = (float*)d_out;
    float* attn = (float*)d_out + (size_t)BB * LL * NH * DD;

    const int smem3 = (5120 + 16384 + 256) * 4;
    cudaFuncSetAttribute(k_scores, cudaFuncAttributeMaxDynamicSharedMemorySize, SMEM1_BYTES);
    cudaFuncSetAttribute(k_pv,     cudaFuncAttributeMaxDynamicSharedMemorySize, smem3);

    dim3 g1(BB * NH, LL / TJ, LL / TI);
    k_scores<<<g1, 256, SMEM1_BYTES>>>(q, k, mask);

    k_comb<<<NROWS / 256, 256>>>();

    dim3 g3(LL / 16, BB);
    k_pv<<<g3, 512, smem3>>>(attn, v, ctx);
}

// round 8
// speedup vs baseline: 2.5318x; 1.8930x over previous
#include <cuda_runtime.h>
#include <cuda_bf16.h>
#include <math_constants.h>
#include <cstdint>

#define BB 2
#define LL 2048
#define NH 16
#define DD 64
#define SCALE 0.125f

#define TI 128
#define TJ 128
#define NTJ (LL / TJ)            // 16 j-tiles
#define NROWS (BB * NH * LL)     // 65536 softmax rows
#define PCH 72                   // smem pitch in bf16 (144B rows -> conflict-free LDSM)

// scores scratch: u = exp(masked scaled score), layout [b][n][i][j]
__device__ float g_scores[(size_t)BB * NH * LL * LL];
// per-(row, j-tile) partial sums of u, layout [jt][b][n][i]
__device__ float g_tl[NTJ * NROWS];
// final per-row 1/sum, layout [b][i][n]
__device__ float g_c[BB * LL * NH];
// pre-split V, layout [b][n][j][d]
__device__ __nv_bfloat16 g_vh[(size_t)BB * NH * LL * DD];
__device__ __nv_bfloat16 g_vl[(size_t)BB * NH * LL * DD];

// ---------------- portable tensor helpers (sm_80+) ----------------
__device__ __forceinline__ uint32_t smem_u32(const void* p) {
    uint32_t a;
    asm("{ .reg .u64 t; cvta.to.shared.u64 t, %1; cvt.u32.u64 %0, t; }" : "=r"(a) : "l"(p));
    return a;
}
__device__ __forceinline__ void ldmatrix_x4(uint32_t& r0, uint32_t& r1,
                                            uint32_t& r2, uint32_t& r3, uint32_t addr) {
    asm volatile("ldmatrix.sync.aligned.m8n8.x4.shared.b16 {%0,%1,%2,%3}, [%4];"
                 : "=r"(r0), "=r"(r1), "=r"(r2), "=r"(r3) : "r"(addr));
}
__device__ __forceinline__ void ldmatrix_x4_t(uint32_t& r0, uint32_t& r1,
                                              uint32_t& r2, uint32_t& r3, uint32_t addr) {
    asm volatile("ldmatrix.sync.aligned.m8n8.x4.trans.shared.b16 {%0,%1,%2,%3}, [%4];"
                 : "=r"(r0), "=r"(r1), "=r"(r2), "=r"(r3) : "r"(addr));
}
__device__ __forceinline__ void mma_bf16(float4& d, const uint32_t a[4],
                                         uint32_t b0, uint32_t b1) {
    asm volatile(
        "mma.sync.aligned.m16n8k16.row.col.f32.bf16.bf16.f32 "
        "{%0,%1,%2,%3},{%4,%5,%6,%7},{%8,%9},{%0,%1,%2,%3};"
        : "+f"(d.x), "+f"(d.y), "+f"(d.z), "+f"(d.w)
        : "r"(a[0]), "r"(a[1]), "r"(a[2]), "r"(a[3]), "r"(b0), "r"(b1));
}

// smem element offsets for k_scores (bf16 units)
#define QHI_OFF 0
#define QLO_OFF (TI * PCH)
#define KHI_OFF (2 * TI * PCH)
#define KLO_OFF (2 * TI * PCH + TJ * PCH)
#define SMEM1_BYTES ((2 * TI * PCH + 2 * TJ * PCH) * 2)   // 73728 B

// ---------------------------------------------------------------------------
// Kernel 1: HMMA scores (unchanged from round 7).
// ---------------------------------------------------------------------------
__global__ __launch_bounds__(256, 2) void k_scores(
    const float* __restrict__ q, const float* __restrict__ k,
    const int* __restrict__ mask)
{
    extern __shared__ __nv_bfloat16 sb[];
    __shared__ float s_l[2][TI];

    const int b  = blockIdx.x >> 4;
    const int n  = blockIdx.x & 15;
    const int j0 = blockIdx.y * TJ;
    const int jt = blockIdx.y;
    const int i0 = blockIdx.z * TI;
    const int tid  = threadIdx.x;
    const int w    = tid >> 5;
    const int lane = tid & 31;
    const int wi = w >> 1;
    const int wj = w & 1;

    for (int idx = tid; idx < TI * 32; idx += 256) {
        int d2 = idx & 31, r = idx >> 5;
        float2 xq = *(const float2*)&q[(((size_t)(b * LL + i0 + r)) * NH + n) * DD + d2 * 2];
        float2 xk = *(const float2*)&k[(((size_t)(b * LL + j0 + r)) * NH + n) * DD + d2 * 2];
        __nv_bfloat16 qh0 = __float2bfloat16_rn(xq.x), qh1 = __float2bfloat16_rn(xq.y);
        __nv_bfloat16 kh0 = __float2bfloat16_rn(xk.x), kh1 = __float2bfloat16_rn(xk.y);
        __nv_bfloat16 ql0 = __float2bfloat16_rn(xq.x - __bfloat162float(qh0));
        __nv_bfloat16 ql1 = __float2bfloat16_rn(xq.y - __bfloat162float(qh1));
        __nv_bfloat16 kl0 = __float2bfloat16_rn(xk.x - __bfloat162float(kh0));
        __nv_bfloat16 kl1 = __float2bfloat16_rn(xk.y - __bfloat162float(kh1));
        int o = r * PCH + d2 * 2;
        *(__nv_bfloat162*)&sb[QHI_OFF + o] = __nv_bfloat162(qh0, qh1);
        *(__nv_bfloat162*)&sb[QLO_OFF + o] = __nv_bfloat162(ql0, ql1);
        *(__nv_bfloat162*)&sb[KHI_OFF + o] = __nv_bfloat162(kh0, kh1);
        *(__nv_bfloat162*)&sb[KLO_OFF + o] = __nv_bfloat162(kl0, kl1);
    }
    __syncthreads();

    float4 acc[2][8];
#pragma unroll
    for (int f = 0; f < 2; f++)
#pragma unroll
        for (int jf = 0; jf < 8; jf++) acc[f][jf] = make_float4(0.f, 0.f, 0.f, 0.f);

    const int a_row = wi * 32 + (lane & 15);
    const int a_kof = (lane >> 4) << 3;
    const int b_row = wj * 64 + ((lane >> 4) << 3) + (lane & 7);
    const int b_kof = ((lane >> 3) & 1) << 3;

#pragma unroll
    for (int ks = 0; ks < 4; ks++) {
        const int k0 = ks * 16;
        uint32_t ah[2][4], al[2][4];
#pragma unroll
        for (int f = 0; f < 2; f++) {
            uint32_t aaddr = smem_u32(&sb[QHI_OFF + (a_row + f * 16) * PCH + k0 + a_kof]);
            ldmatrix_x4(ah[f][0], ah[f][1], ah[f][2], ah[f][3], aaddr);
            uint32_t laddr = smem_u32(&sb[QLO_OFF + (a_row + f * 16) * PCH + k0 + a_kof]);
            ldmatrix_x4(al[f][0], al[f][1], al[f][2], al[f][3], laddr);
        }
#pragma unroll
        for (int jp = 0; jp < 4; jp++) {
            uint32_t bh0, bh1, bh2, bh3, bl0, bl1, bl2, bl3;
            uint32_t bha = smem_u32(&sb[KHI_OFF + (b_row + jp * 16) * PCH + k0 + b_kof]);
            uint32_t bla = smem_u32(&sb[KLO_OFF + (b_row + jp * 16) * PCH + k0 + b_kof]);
            ldmatrix_x4(bh0, bh1, bh2, bh3, bha);
            ldmatrix_x4(bl0, bl1, bl2, bl3, bla);
#pragma unroll
            for (int f = 0; f < 2; f++) {
                mma_bf16(acc[f][jp * 2],     ah[f], bh0, bh1);
                mma_bf16(acc[f][jp * 2],     ah[f], bl0, bl1);
                mma_bf16(acc[f][jp * 2],     al[f], bh0, bh1);
                mma_bf16(acc[f][jp * 2 + 1], ah[f], bh2, bh3);
                mma_bf16(acc[f][jp * 2 + 1], ah[f], bl2, bl3);
                mma_bf16(acc[f][jp * 2 + 1], al[f], bh2, bh3);
            }
        }
    }

    const int qr = lane >> 2, qc = (lane & 3) * 2;
    float ls[2][2] = {{0.f, 0.f}, {0.f, 0.f}};
#pragma unroll
    for (int f = 0; f < 2; f++) {
        const int r0 = i0 + wi * 32 + f * 16 + qr;
        const size_t mrow0 = (size_t)(b * LL + r0) * LL;
        const size_t srow0 = ((size_t)(b * NH + n) * LL + r0) * LL;
#pragma unroll
        for (int jf = 0; jf < 8; jf++) {
            const int col = j0 + wj * 64 + jf * 8 + qc;
            float4 a = acc[f][jf];
            int2 m0 = *(const int2*)&mask[mrow0 + col];
            int2 m1 = *(const int2*)&mask[mrow0 + 8 * LL + col];
            float2 u0, u1;
            u0.x = m0.x ? 0.f : __expf(a.x * SCALE);
            u0.y = m0.y ? 0.f : __expf(a.y * SCALE);
            u1.x = m1.x ? 0.f : __expf(a.z * SCALE);
            u1.y = m1.y ? 0.f : __expf(a.w * SCALE);
            *(float2*)&g_scores[srow0 + col] = u0;
            *(float2*)&g_scores[srow0 + 8 * LL + col] = u1;
            ls[f][0] += u0.x + u0.y;
            ls[f][1] += u1.x + u1.y;
        }
    }
#pragma unroll
    for (int f = 0; f < 2; f++)
#pragma unroll
        for (int h = 0; h < 2; h++) {
            float v = ls[f][h];
            v += __shfl_xor_sync(0xffffffffu, v, 1);
            v += __shfl_xor_sync(0xffffffffu, v, 2);
            ls[f][h] = v;
        }
    if ((lane & 3) == 0) {
#pragma unroll
        for (int f = 0; f < 2; f++)
#pragma unroll
            for (int h = 0; h < 2; h++)
                s_l[wj][wi * 32 + f * 16 + h * 8 + qr] = ls[f][h];
    }
    __syncthreads();
    if (tid < TI) {
        float L = s_l[0][tid] + s_l[1][tid];
        g_tl[(size_t)jt * NROWS + (size_t)(b * NH + n) * LL + i0 + tid] = L;
    }
}

// ---------------------------------------------------------------------------
// Kernel 2: combine tile sums -> g_c = 1/L.
// ---------------------------------------------------------------------------
__global__ __launch_bounds__(256) void k_comb()
{
    const int r = blockIdx.x * 256 + threadIdx.x;
    float L = 0.f;
#pragma unroll
    for (int t = 0; t < NTJ; t++) L += g_tl[(size_t)t * NROWS + r];
    const int i = r & (LL - 1);
    const int n = (r >> 11) & (NH - 1);
    const int b = r >> 15;
    g_c[((size_t)(b * LL + i)) * NH + n] = 1.f / L;
}

// ---------------------------------------------------------------------------
// Kernel 2b: split V -> bf16 hi/lo, layout [b][n][j][d]. Both sides coalesced.
// ---------------------------------------------------------------------------
__global__ __launch_bounds__(256) void k_vsplit(const float* __restrict__ v)
{
    int idx = blockIdx.x * 256 + threadIdx.x;   // over BB*NH*LL*32 (d2-pairs)
    int d2 = idx & 31;
    int j  = (idx >> 5) & (LL - 1);
    int n  = (idx >> 16) & 15;
    int b  = idx >> 20;
    float2 x = *(const float2*)&v[(((size_t)(b * LL + j)) * NH + n) * DD + d2 * 2];
    __nv_bfloat16 h0 = __float2bfloat16_rn(x.x), h1 = __float2bfloat16_rn(x.y);
    __nv_bfloat16 l0 = __float2bfloat16_rn(x.x - __bfloat162float(h0));
    __nv_bfloat16 l1 = __float2bfloat16_rn(x.y - __bfloat162float(h1));
    size_t o = (((size_t)(b * NH + n)) * LL + j) * DD + d2 * 2;
    *(__nv_bfloat162*)&g_vh[o] = __nv_bfloat162(h0, h1);
    *(__nv_bfloat162*)&g_vl[o] = __nv_bfloat162(l0, l1);
}

// ---------------------------------------------------------------------------
// Kernel 3: attn output. p = u * c, transpose [b,n,i,j] -> [b,i,j,n] via smem.
// CTA: 32i x 32j x 16n tile.
// ---------------------------------------------------------------------------
__global__ __launch_bounds__(256, 2) void k_attn(float* __restrict__ attn)
{
    extern __shared__ float S[];       // [32*32][17]
    __shared__ float Cs[512];          // [32 ii][16 n]
    const int b = blockIdx.z, i0 = blockIdx.y * 32, j0 = blockIdx.x * 32;
    const int tid = threadIdx.x;

    for (int t = tid; t < 512; t += 256) {
        int ii = t >> 4, n = t & 15;
        Cs[t] = g_c[((size_t)(b * LL + i0 + ii)) * NH + n];
    }
    __syncthreads();
#pragma unroll
    for (int kk = 0; kk < 16; kk++) {
        int idx = tid + kk * 256;          // 4096 float4
        int jf4 = idx & 7, ii = (idx >> 3) & 31, n = idx >> 8;
        float4 u = *(const float4*)&g_scores[
            (((size_t)(b * NH + n)) * LL + i0 + ii) * LL + j0 + jf4 * 4];
        float c = Cs[ii * 16 + n];
        int base = (ii * 32 + jf4 * 4) * 17 + n;
        S[base] = u.x * c; S[base + 17] = u.y * c;
        S[base + 34] = u.z * c; S[base + 51] = u.w * c;
    }
    __syncthreads();
#pragma unroll
    for (int kk = 0; kk < 64; kk++) {
        int idx = tid + kk * 256;          // 16384 floats
        int n = idx & 15, jj = (idx >> 4) & 31, ii = idx >> 9;
        attn[(((size_t)(b * LL + i0 + ii)) * LL + j0 + jj) * NH + n] =
            S[(ii * 32 + jj) * 17 + n];
    }
}

// ---------------------------------------------------------------------------
// Kernel 4: tensor PV. CTA = (b,n) x 128 i. 8 warps, warp = 16 i x 64 d.
// bf16x3: ctx += Phi*Vhi + Phi*Vlo + Plo*Vhi.
// ---------------------------------------------------------------------------
#define PVH_OFF 0
#define PVL_OFF (128 * PCH)
#define VVH_OFF (2 * 128 * PCH)
#define VVL_OFF (2 * 128 * PCH + 64 * PCH)
#define SMEM4_BYTES ((2 * 128 * PCH + 2 * 64 * PCH) * 2)  // 55296 B

__global__ __launch_bounds__(256, 2) void k_pvt(float* __restrict__ ctx)
{
    extern __shared__ __nv_bfloat16 pb[];
    __shared__ float sc[128];

    const int bn = blockIdx.x;           // b*16+n
    const int b = bn >> 4, n = bn & 15;
    const int i0 = blockIdx.y * 128;
    const int tid = threadIdx.x, w = tid >> 5, lane = tid & 31;

    if (tid < 128) sc[tid] = g_c[((size_t)(b * LL + i0 + tid)) * NH + n];

    float4 acc[8];
#pragma unroll
    for (int g = 0; g < 8; g++) acc[g] = make_float4(0.f, 0.f, 0.f, 0.f);

    const size_t ubase = ((size_t)bn * LL + i0) * LL;
    const size_t vbase = (size_t)bn * LL * DD;

    // ldmatrix addresses (constant per thread)
    const int a_row = w * 16 + (lane & 15);
    const int a_kof = (lane >> 4) << 3;
    const int v_rof = ((lane >> 3) & 1) * 8 + (lane & 7);
    const int v_cof = (lane >> 4) * 8;

    __syncthreads();

    for (int j0 = 0; j0 < LL; j0 += 64) {
        // stage V hi/lo tiles [64 j][64 d]
        for (int t = tid; t < 512; t += 256) {
            int r = t >> 3, c4 = t & 7;
            *(uint4*)&pb[VVH_OFF + r * PCH + c4 * 8] =
                *(const uint4*)&g_vh[vbase + (size_t)(j0 + r) * DD + c4 * 8];
            *(uint4*)&pb[VVL_OFF + r * PCH + c4 * 8] =
                *(const uint4*)&g_vl[vbase + (size_t)(j0 + r) * DD + c4 * 8];
        }
        // stage P hi/lo [128 i][64 j]: p = u * c
#pragma unroll
        for (int t = 0; t < 8; t++) {
            int idx = tid + t * 256;       // 2048 float4
            int row = idx >> 4, c4 = idx & 15;
            float4 u = *(const float4*)&g_scores[ubase + (size_t)row * LL + j0 + c4 * 4];
            float c = sc[row];
            float px = u.x * c, py = u.y * c, pz = u.z * c, pw = u.w * c;
            __nv_bfloat16 hx = __float2bfloat16_rn(px), hy = __float2bfloat16_rn(py);
            __nv_bfloat16 hz = __float2bfloat16_rn(pz), hw = __float2bfloat16_rn(pw);
            __nv_bfloat16 lx = __float2bfloat16_rn(px - __bfloat162float(hx));
            __nv_bfloat16 ly = __float2bfloat16_rn(py - __bfloat162float(hy));
            __nv_bfloat16 lz = __float2bfloat16_rn(pz - __bfloat162float(hz));
            __nv_bfloat16 lw = __float2bfloat16_rn(pw - __bfloat162float(hw));
            int o = row * PCH + c4 * 4;
            *(__nv_bfloat162*)&pb[PVH_OFF + o]     = __nv_bfloat162(hx, hy);
            *(__nv_bfloat162*)&pb[PVH_OFF + o + 2] = __nv_bfloat162(hz, hw);
            *(__nv_bfloat162*)&pb[PVL_OFF + o]     = __nv_bfloat162(lx, ly);
            *(__nv_bfloat162*)&pb[PVL_OFF + o + 2] = __nv_bfloat162(lz, lw);
        }
        __syncthreads();

#pragma unroll
        for (int ks = 0; ks < 4; ks++) {
            const int k0 = ks * 16;
            uint32_t ah[4], al[4];
            ldmatrix_x4(ah[0], ah[1], ah[2], ah[3],
                        smem_u32(&pb[PVH_OFF + a_row * PCH + k0 + a_kof]));
            ldmatrix_x4(al[0], al[1], al[2], al[3],
                        smem_u32(&pb[PVL_OFF + a_row * PCH + k0 + a_kof]));
#pragma unroll
            for (int ng = 0; ng < 4; ng++) {
                uint32_t bh0, bh1, bh2, bh3, bl0, bl1, bl2, bl3;
                const int voff = (k0 + v_rof) * PCH + ng * 16 + v_cof;
                ldmatrix_x4_t(bh0, bh1, bh2, bh3, smem_u32(&pb[VVH_OFF + voff]));
                ldmatrix_x4_t(bl0, bl1, bl2, bl3, smem_u32(&pb[VVL_OFF + voff]));
                mma_bf16(acc[ng * 2],     ah, bh0, bh1);
                mma_bf16(acc[ng * 2],     ah, bl0, bl1);
                mma_bf16(acc[ng * 2],     al, bh0, bh1);
                mma_bf16(acc[ng * 2 + 1], ah, bh2, bh3);
                mma_bf16(acc[ng * 2 + 1], ah, bl2, bl3);
                mma_bf16(acc[ng * 2 + 1], al, bh2, bh3);
            }
        }
        __syncthreads();
    }

    // write ctx [b][i][n][d]
    const int r = w * 16 + (lane >> 2);
#pragma unroll
    for (int ng = 0; ng < 8; ng++) {
        int colb = ng * 8 + (lane & 3) * 2;
        size_t g0 = (((size_t)(b * LL + i0 + r)) * NH + n) * DD + colb;
        size_t g1 = (((size_t)(b * LL + i0 + r + 8)) * NH + n) * DD + colb;
        *(float2*)&ctx[g0] = make_float2(acc[ng].x, acc[ng].y);
        *(float2*)&ctx[g1] = make_float2(acc[ng].z, acc[ng].w);
    }
}

// ---------------------------------------------------------------------------
extern "C" void kernel_launch(void* const* d_in, const int* in_sizes, int n_in,
                              void* d_out, int out_size)
{
    const float* q = (const float*)d_in[0];
    const float* k = (const float*)d_in[1];
    const float* v = (const float*)d_in[2];
    const int* mask = (const int*)d_in[3];

    float* ctx  = (float*)d_out;
    float* attn = (float*)d_out + (size_t)BB * LL * NH * DD;

    const int smem_attn = (32 * 32 * 17) * 4;   // 69632 B
    cudaFuncSetAttribute(k_scores, cudaFuncAttributeMaxDynamicSharedMemorySize, SMEM1_BYTES);
    cudaFuncSetAttribute(k_attn,   cudaFuncAttributeMaxDynamicSharedMemorySize, smem_attn);
    cudaFuncSetAttribute(k_pvt,    cudaFuncAttributeMaxDynamicSharedMemorySize, SMEM4_BYTES);

    k_vsplit<<<(BB * NH * LL * 32) / 256, 256>>>(v);

    dim3 g1(BB * NH, LL / TJ, LL / TI);
    k_scores<<<g1, 256, SMEM1_BYTES>>>(q, k, mask);

    k_comb<<<NROWS / 256, 256>>>();

    dim3 ga(LL / 32, LL / 32, BB);
    k_attn<<<ga, 256, smem_attn>>>(attn);

    dim3 gp(BB * NH, LL / 128);
    k_pvt<<<gp, 256, SMEM4_BYTES>>>(ctx);
}

// round 9
// speedup vs baseline: 3.0324x; 1.1977x over previous
#include <cuda_runtime.h>
#include <cuda_bf16.h>
#include <cuda_fp16.h>
#include <math_constants.h>
#include <cstdint>

#define BB 2
#define LL 2048
#define NH 16
#define DD 64
#define SCALE 0.125f

#define TI 128
#define TJ 128
#define NTJ (LL / TJ)            // 16 j-tiles
#define NROWS (BB * NH * LL)     // 65536 softmax rows
#define PCH 72                   // smem pitch in 16-bit elems (144B rows -> conflict-free LDSM)

// scores scratch: u = exp(masked scaled score) in fp16, layout [b][n][i][j]
__device__ __half g_scores[(size_t)BB * NH * LL * LL];
// per-(row, j-tile) partial sums of u, layout [jt][b][n][i]
__device__ float g_tl[NTJ * NROWS];
// final per-row 1/sum, layout [b][i][n]
__device__ float g_c[BB * LL * NH];
// pre-split Q/K (bf16 hi/lo) and V (fp16 hi/lo), layout [b][n][j][d]
__device__ __nv_bfloat16 g_qh[(size_t)BB * NH * LL * DD];
__device__ __nv_bfloat16 g_ql[(size_t)BB * NH * LL * DD];
__device__ __nv_bfloat16 g_kh[(size_t)BB * NH * LL * DD];
__device__ __nv_bfloat16 g_kl[(size_t)BB * NH * LL * DD];
__device__ __half g_vh[(size_t)BB * NH * LL * DD];
__device__ __half g_vl[(size_t)BB * NH * LL * DD];

// ---------------- portable tensor helpers (sm_80+) ----------------
__device__ __forceinline__ uint32_t smem_u32(const void* p) {
    uint32_t a;
    asm("{ .reg .u64 t; cvta.to.shared.u64 t, %1; cvt.u32.u64 %0, t; }" : "=r"(a) : "l"(p));
    return a;
}
__device__ __forceinline__ void ldmatrix_x4(uint32_t& r0, uint32_t& r1,
                                            uint32_t& r2, uint32_t& r3, uint32_t addr) {
    asm volatile("ldmatrix.sync.aligned.m8n8.x4.shared.b16 {%0,%1,%2,%3}, [%4];"
                 : "=r"(r0), "=r"(r1), "=r"(r2), "=r"(r3) : "r"(addr));
}
__device__ __forceinline__ void ldmatrix_x4_t(uint32_t& r0, uint32_t& r1,
                                              uint32_t& r2, uint32_t& r3, uint32_t addr) {
    asm volatile("ldmatrix.sync.aligned.m8n8.x4.trans.shared.b16 {%0,%1,%2,%3}, [%4];"
                 : "=r"(r0), "=r"(r1), "=r"(r2), "=r"(r3) : "r"(addr));
}
__device__ __forceinline__ void mma_bf16(float4& d, const uint32_t a[4],
                                         uint32_t b0, uint32_t b1) {
    asm volatile(
        "mma.sync.aligned.m16n8k16.row.col.f32.bf16.bf16.f32 "
        "{%0,%1,%2,%3},{%4,%5,%6,%7},{%8,%9},{%0,%1,%2,%3};"
        : "+f"(d.x), "+f"(d.y), "+f"(d.z), "+f"(d.w)
        : "r"(a[0]), "r"(a[1]), "r"(a[2]), "r"(a[3]), "r"(b0), "r"(b1));
}
__device__ __forceinline__ void mma_f16(float4& d, const uint32_t a[4],
                                        uint32_t b0, uint32_t b1) {
    asm volatile(
        "mma.sync.aligned.m16n8k16.row.col.f32.f16.f16.f32 "
        "{%0,%1,%2,%3},{%4,%5,%6,%7},{%8,%9},{%0,%1,%2,%3};"
        : "+f"(d.x), "+f"(d.y), "+f"(d.z), "+f"(d.w)
        : "r"(a[0]), "r"(a[1]), "r"(a[2]), "r"(a[3]), "r"(b0), "r"(b1));
}

// ---------------------------------------------------------------------------
// Kernel 0: split Q,K -> bf16 hi/lo; V -> fp16 hi/lo. [b,i,n,d] -> [b,n,i,d].
// ---------------------------------------------------------------------------
__global__ __launch_bounds__(256) void k_split(
    const float* __restrict__ q, const float* __restrict__ k,
    const float* __restrict__ v)
{
    int idx = blockIdx.x * 256 + threadIdx.x;   // BB*NH*LL*32
    int d2 = idx & 31;
    int j  = (idx >> 5) & (LL - 1);
    int n  = (idx >> 16) & 15;
    int b  = idx >> 20;
    size_t src = (((size_t)(b * LL + j)) * NH + n) * DD + d2 * 2;
    size_t dst = (((size_t)(b * NH + n)) * LL + j) * DD + d2 * 2;

    float2 xq = *(const float2*)&q[src];
    float2 xk = *(const float2*)&k[src];
    float2 xv = *(const float2*)&v[src];

    __nv_bfloat16 qh0 = __float2bfloat16_rn(xq.x), qh1 = __float2bfloat16_rn(xq.y);
    __nv_bfloat16 kh0 = __float2bfloat16_rn(xk.x), kh1 = __float2bfloat16_rn(xk.y);
    *(__nv_bfloat162*)&g_qh[dst] = __nv_bfloat162(qh0, qh1);
    *(__nv_bfloat162*)&g_kh[dst] = __nv_bfloat162(kh0, kh1);
    *(__nv_bfloat162*)&g_ql[dst] = __nv_bfloat162(
        __float2bfloat16_rn(xq.x - __bfloat162float(qh0)),
        __float2bfloat16_rn(xq.y - __bfloat162float(qh1)));
    *(__nv_bfloat162*)&g_kl[dst] = __nv_bfloat162(
        __float2bfloat16_rn(xk.x - __bfloat162float(kh0)),
        __float2bfloat16_rn(xk.y - __bfloat162float(kh1)));

    __half vh0 = __float2half_rn(xv.x), vh1 = __float2half_rn(xv.y);
    *(__half2*)&g_vh[dst] = __half2(vh0, vh1);
    *(__half2*)&g_vl[dst] = __half2(
        __float2half_rn(xv.x - __half2float(vh0)),
        __float2half_rn(xv.y - __half2float(vh1)));
}

// smem element offsets for k_scores (bf16 units)
#define QHI_OFF 0
#define QLO_OFF (TI * PCH)
#define KHI_OFF (2 * TI * PCH)
#define KLO_OFF (2 * TI * PCH + TJ * PCH)
#define SMEM1_BYTES ((2 * TI * PCH + 2 * TJ * PCH) * 2)   // 73728 B

// ---------------------------------------------------------------------------
// Kernel 1: HMMA scores (bf16x3), fp16 u output + row partial sums.
// ---------------------------------------------------------------------------
__global__ __launch_bounds__(256, 2) void k_scores(const int* __restrict__ mask)
{
    extern __shared__ __nv_bfloat16 sb[];
    __shared__ float s_l[2][TI];

    const int b  = blockIdx.x >> 4;
    const int n  = blockIdx.x & 15;
    const int j0 = blockIdx.y * TJ;
    const int jt = blockIdx.y;
    const int i0 = blockIdx.z * TI;
    const int tid  = threadIdx.x;
    const int w    = tid >> 5;
    const int lane = tid & 31;
    const int wi = w >> 1;
    const int wj = w & 1;

    // ---- stage pre-split tiles (bf16, no conversion) ----
    const size_t qbase = ((size_t)(b * NH + n) * LL + i0) * DD;
    const size_t kbase = ((size_t)(b * NH + n) * LL + j0) * DD;
    for (int t = tid; t < 1024; t += 256) {
        int r = t >> 3, c8 = t & 7;
        int o = r * PCH + c8 * 8;
        size_t gq = qbase + (size_t)r * DD + c8 * 8;
        size_t gk = kbase + (size_t)r * DD + c8 * 8;
        *(uint4*)&sb[QHI_OFF + o] = *(const uint4*)&g_qh[gq];
        *(uint4*)&sb[QLO_OFF + o] = *(const uint4*)&g_ql[gq];
        *(uint4*)&sb[KHI_OFF + o] = *(const uint4*)&g_kh[gk];
        *(uint4*)&sb[KLO_OFF + o] = *(const uint4*)&g_kl[gk];
    }
    __syncthreads();

    float4 acc[2][8];
#pragma unroll
    for (int f = 0; f < 2; f++)
#pragma unroll
        for (int jf = 0; jf < 8; jf++) acc[f][jf] = make_float4(0.f, 0.f, 0.f, 0.f);

    const int a_row = wi * 32 + (lane & 15);
    const int a_kof = (lane >> 4) << 3;
    const int b_row = wj * 64 + ((lane >> 4) << 3) + (lane & 7);
    const int b_kof = ((lane >> 3) & 1) << 3;

#pragma unroll
    for (int ks = 0; ks < 4; ks++) {
        const int k0 = ks * 16;
        uint32_t ah[2][4], al[2][4];
#pragma unroll
        for (int f = 0; f < 2; f++) {
            ldmatrix_x4(ah[f][0], ah[f][1], ah[f][2], ah[f][3],
                        smem_u32(&sb[QHI_OFF + (a_row + f * 16) * PCH + k0 + a_kof]));
            ldmatrix_x4(al[f][0], al[f][1], al[f][2], al[f][3],
                        smem_u32(&sb[QLO_OFF + (a_row + f * 16) * PCH + k0 + a_kof]));
        }
#pragma unroll
        for (int jp = 0; jp < 4; jp++) {
            uint32_t bh0, bh1, bh2, bh3, bl0, bl1, bl2, bl3;
            ldmatrix_x4(bh0, bh1, bh2, bh3,
                        smem_u32(&sb[KHI_OFF + (b_row + jp * 16) * PCH + k0 + b_kof]));
            ldmatrix_x4(bl0, bl1, bl2, bl3,
                        smem_u32(&sb[KLO_OFF + (b_row + jp * 16) * PCH + k0 + b_kof]));
#pragma unroll
            for (int f = 0; f < 2; f++) {
                mma_bf16(acc[f][jp * 2],     ah[f], bh0, bh1);
                mma_bf16(acc[f][jp * 2],     ah[f], bl0, bl1);
                mma_bf16(acc[f][jp * 2],     al[f], bh0, bh1);
                mma_bf16(acc[f][jp * 2 + 1], ah[f], bh2, bh3);
                mma_bf16(acc[f][jp * 2 + 1], ah[f], bl2, bl3);
                mma_bf16(acc[f][jp * 2 + 1], al[f], bh2, bh3);
            }
        }
    }

    // ---- epilogue: u = exp(s) (masked -> 0), fp16 store, row partial sums ----
    const int qr = lane >> 2, qc = (lane & 3) * 2;
    float ls[2][2] = {{0.f, 0.f}, {0.f, 0.f}};
#pragma unroll
    for (int f = 0; f < 2; f++) {
        const int r0 = i0 + wi * 32 + f * 16 + qr;
        const size_t mrow0 = (size_t)(b * LL + r0) * LL;
        const size_t srow0 = ((size_t)(b * NH + n) * LL + r0) * LL;
#pragma unroll
        for (int jf = 0; jf < 8; jf++) {
            const int col = j0 + wj * 64 + jf * 8 + qc;
            float4 a = acc[f][jf];
            int2 m0 = *(const int2*)&mask[mrow0 + col];
            int2 m1 = *(const int2*)&mask[mrow0 + 8 * LL + col];
            float2 u0, u1;
            u0.x = m0.x ? 0.f : __expf(a.x * SCALE);
            u0.y = m0.y ? 0.f : __expf(a.y * SCALE);
            u1.x = m1.x ? 0.f : __expf(a.z * SCALE);
            u1.y = m1.y ? 0.f : __expf(a.w * SCALE);
            *(__half2*)&g_scores[srow0 + col] = __floats2half2_rn(u0.x, u0.y);
            *(__half2*)&g_scores[srow0 + 8 * LL + col] = __floats2half2_rn(u1.x, u1.y);
            ls[f][0] += u0.x + u0.y;
            ls[f][1] += u1.x + u1.y;
        }
    }
#pragma unroll
    for (int f = 0; f < 2; f++)
#pragma unroll
        for (int h = 0; h < 2; h++) {
            float vv = ls[f][h];
            vv += __shfl_xor_sync(0xffffffffu, vv, 1);
            vv += __shfl_xor_sync(0xffffffffu, vv, 2);
            ls[f][h] = vv;
        }
    if ((lane & 3) == 0) {
#pragma unroll
        for (int f = 0; f < 2; f++)
#pragma unroll
            for (int h = 0; h < 2; h++)
                s_l[wj][wi * 32 + f * 16 + h * 8 + qr] = ls[f][h];
    }
    __syncthreads();
    if (tid < TI) {
        float L = s_l[0][tid] + s_l[1][tid];
        g_tl[(size_t)jt * NROWS + (size_t)(b * NH + n) * LL + i0 + tid] = L;
    }
}

// ---------------------------------------------------------------------------
// Kernel 2: combine tile sums -> g_c = 1/L.
// ---------------------------------------------------------------------------
__global__ __launch_bounds__(256) void k_comb()
{
    const int r = blockIdx.x * 256 + threadIdx.x;
    float L = 0.f;
#pragma unroll
    for (int t = 0; t < NTJ; t++) L += g_tl[(size_t)t * NROWS + r];
    const int i = r & (LL - 1);
    const int n = (r >> 11) & (NH - 1);
    const int b = r >> 15;
    g_c[((size_t)(b * LL + i)) * NH + n] = 1.f / L;
}

// ---------------------------------------------------------------------------
// Kernel 3: attn output. p = u * c, transpose [b,n,i,j](fp16) -> [b,i,j,n](f32).
// CTA: 32i x 32j x 16n tile. S layout [j][ii][pitch 17].
// ---------------------------------------------------------------------------
__global__ __launch_bounds__(256, 2) void k_attn(float* __restrict__ attn)
{
    extern __shared__ float S[];       // [32 j][32 ii][17]
    __shared__ float Cs[512];          // [32 ii][16 n]
    const int b = blockIdx.z, i0 = blockIdx.y * 32, j0 = blockIdx.x * 32;
    const int tid = threadIdx.x;

    for (int t = tid; t < 512; t += 256) {
        int ii = t >> 4, n = t & 15;
        Cs[t] = g_c[((size_t)(b * LL + i0 + ii)) * NH + n];
    }
    __syncthreads();
#pragma unroll
    for (int kk = 0; kk < 8; kk++) {
        int idx = tid + kk * 256;          // 2048 uint4 (8 halves each)
        int c8 = idx & 3, ii = (idx >> 2) & 31, n = idx >> 7;
        uint4 raw = *(const uint4*)&g_scores[
            (((size_t)(b * NH + n)) * LL + i0 + ii) * LL + j0 + c8 * 8];
        const __half2* h2 = (const __half2*)&raw;
        float c = Cs[ii * 16 + n];
#pragma unroll
        for (int t = 0; t < 4; t++) {
            float2 f = __half22float2(h2[t]);
            int jloc = c8 * 8 + t * 2;
            S[(jloc * 32 + ii) * 17 + n] = f.x * c;
            S[((jloc + 1) * 32 + ii) * 17 + n] = f.y * c;
        }
    }
    __syncthreads();
#pragma unroll
    for (int kk = 0; kk < 64; kk++) {
        int idx = tid + kk * 256;          // 16384 floats
        int n = idx & 15, jj = (idx >> 4) & 31, ii = idx >> 9;
        attn[(((size_t)(b * LL + i0 + ii)) * LL + j0 + jj) * NH + n] =
            S[(jj * 32 + ii) * 17 + n];
    }
}

// ---------------------------------------------------------------------------
// Kernel 4: tensor PV on raw fp16 u (normalization deferred to epilogue).
// CTA = (b,n) x 128 i. 8 warps, warp = 16 i x 64 d. ctx = c * (P_f16 @ (Vhi+Vlo)).
// ---------------------------------------------------------------------------
#define PVH_OFF 0
#define VVH_OFF (128 * PCH)
#define VVL_OFF (128 * PCH + 64 * PCH)
#define SMEM4_BYTES ((128 * PCH + 2 * 64 * PCH) * 2)  // 36864 B

__global__ __launch_bounds__(256, 3) void k_pvt(float* __restrict__ ctx)
{
    extern __shared__ __half pb[];

    const int bn = blockIdx.x;           // b*16+n
    const int b = bn >> 4, n = bn & 15;
    const int i0 = blockIdx.y * 128;
    const int tid = threadIdx.x, w = tid >> 5, lane = tid & 31;

    float4 acc[8];
#pragma unroll
    for (int g = 0; g < 8; g++) acc[g] = make_float4(0.f, 0.f, 0.f, 0.f);

    const size_t ubase = ((size_t)bn * LL + i0) * LL;
    const size_t vbase = (size_t)bn * LL * DD;

    const int a_row = w * 16 + (lane & 15);
    const int a_kof = (lane >> 4) << 3;
    const int v_rof = ((lane >> 3) & 1) * 8 + (lane & 7);
    const int v_cof = (lane >> 4) * 8;

    for (int j0 = 0; j0 < LL; j0 += 64) {
        // stage V hi/lo tiles [64 j][64 d] fp16
        for (int t = tid; t < 512; t += 256) {
            int r = t >> 3, c8 = t & 7;
            size_t gv = vbase + (size_t)(j0 + r) * DD + c8 * 8;
            *(uint4*)&pb[VVH_OFF + r * PCH + c8 * 8] = *(const uint4*)&g_vh[gv];
            *(uint4*)&pb[VVL_OFF + r * PCH + c8 * 8] = *(const uint4*)&g_vl[gv];
        }
        // stage raw u tile [128 i][64 j] fp16 (straight copy, no math)
#pragma unroll
        for (int t = 0; t < 4; t++) {
            int idx = tid + t * 256;       // 1024 uint4
            int row = idx >> 3, c8 = idx & 7;
            *(uint4*)&pb[PVH_OFF + row * PCH + c8 * 8] =
                *(const uint4*)&g_scores[ubase + (size_t)row * LL + j0 + c8 * 8];
        }
        __syncthreads();

#pragma unroll
        for (int ks = 0; ks < 4; ks++) {
            const int k0 = ks * 16;
            uint32_t ah[4];
            ldmatrix_x4(ah[0], ah[1], ah[2], ah[3],
                        smem_u32(&pb[PVH_OFF + a_row * PCH + k0 + a_kof]));
#pragma unroll
            for (int ng = 0; ng < 4; ng++) {
                uint32_t bh0, bh1, bh2, bh3, bl0, bl1, bl2, bl3;
                const int voff = (k0 + v_rof) * PCH + ng * 16 + v_cof;
                ldmatrix_x4_t(bh0, bh1, bh2, bh3, smem_u32(&pb[VVH_OFF + voff]));
                ldmatrix_x4_t(bl0, bl1, bl2, bl3, smem_u32(&pb[VVL_OFF + voff]));
                mma_f16(acc[ng * 2],     ah, bh0, bh1);
                mma_f16(acc[ng * 2],     ah, bl0, bl1);
                mma_f16(acc[ng * 2 + 1], ah, bh2, bh3);
                mma_f16(acc[ng * 2 + 1], ah, bl2, bl3);
            }
        }
        __syncthreads();
    }

    // epilogue: scale by c and write ctx [b][i][n][d]
    const int r = w * 16 + (lane >> 2);
    const float c0 = g_c[((size_t)(b * LL + i0 + r)) * NH + n];
    const float c1 = g_c[((size_t)(b * LL + i0 + r + 8)) * NH + n];
#pragma unroll
    for (int ng = 0; ng < 8; ng++) {
        int colb = ng * 8 + (lane & 3) * 2;
        size_t g0 = (((size_t)(b * LL + i0 + r)) * NH + n) * DD + colb;
        size_t g1 = (((size_t)(b * LL + i0 + r + 8)) * NH + n) * DD + colb;
        *(float2*)&ctx[g0] = make_float2(acc[ng].x * c0, acc[ng].y * c0);
        *(float2*)&ctx[g1] = make_float2(acc[ng].z * c1, acc[ng].w * c1);
    }
}

// ---------------------------------------------------------------------------
extern "C" void kernel_launch(void* const* d_in, const int* in_sizes, int n_in,
                              void* d_out, int out_size)
{
    const float* q = (const float*)d_in[0];
    const float* k = (const float*)d_in[1];
    const float* v = (const float*)d_in[2];
    const int* mask = (const int*)d_in[3];

    float* ctx  = (float*)d_out;
    float* attn = (float*)d_out + (size_t)BB * LL * NH * DD;

    const int smem_attn = (32 * 32 * 17) * 4;   // 69632 B
    cudaFuncSetAttribute(k_scores, cudaFuncAttributeMaxDynamicSharedMemorySize, SMEM1_BYTES);
    cudaFuncSetAttribute(k_attn,   cudaFuncAttributeMaxDynamicSharedMemorySize, smem_attn);

    k_split<<<(BB * NH * LL * 32) / 256, 256>>>(q, k, v);

    dim3 g1(BB * NH, LL / TJ, LL / TI);
    k_scores<<<g1, 256, SMEM1_BYTES>>>(mask);

    k_comb<<<NROWS / 256, 256>>>();

    dim3 ga(LL / 32, LL / 32, BB);
    k_attn<<<ga, 256, smem_attn>>>(attn);

    dim3 gp(BB * NH, LL / 128);
    k_pvt<<<gp, 256, SMEM4_BYTES>>>(ctx);
}

// round 10
// speedup vs baseline: 3.3827x; 1.1155x over previous
#include <cuda_runtime.h>
#include <cuda_bf16.h>
#include <cuda_fp16.h>
#include <math_constants.h>
#include <cstdint>

#define BB 2
#define LL 2048
#define NH 16
#define DD 64
#define SCALE 0.125f

#define TI 128
#define TJ 64
#define NTJ (LL / TJ)            // 32 j-tiles
#define NROWS (BB * NH * LL)     // 65536 softmax rows
#define PCH 72                   // smem pitch in 16-bit elems (144B rows -> conflict-free LDSM)

// scores scratch: u = exp(masked scaled score) in fp16, layout [b][n][i][j]
__device__ __half g_scores[(size_t)BB * NH * LL * LL];
// per-(row, j-tile) partial sums of u, layout [jt][b][n][i]
__device__ float g_tl[NTJ * NROWS];
// final per-row 1/sum, layout [b][i][n]
__device__ float g_c[BB * LL * NH];
// pre-split Q/K (bf16 hi/lo) and V (fp16 hi/lo), layout [b][n][j][d]
__device__ __nv_bfloat16 g_qh[(size_t)BB * NH * LL * DD];
__device__ __nv_bfloat16 g_ql[(size_t)BB * NH * LL * DD];
__device__ __nv_bfloat16 g_kh[(size_t)BB * NH * LL * DD];
__device__ __nv_bfloat16 g_kl[(size_t)BB * NH * LL * DD];
__device__ __half g_vh[(size_t)BB * NH * LL * DD];
__device__ __half g_vl[(size_t)BB * NH * LL * DD];

// ---------------- portable tensor helpers (sm_80+) ----------------
__device__ __forceinline__ uint32_t smem_u32(const void* p) {
    uint32_t a;
    asm("{ .reg .u64 t; cvta.to.shared.u64 t, %1; cvt.u32.u64 %0, t; }" : "=r"(a) : "l"(p));
    return a;
}
__device__ __forceinline__ void ldmatrix_x4(uint32_t& r0, uint32_t& r1,
                                            uint32_t& r2, uint32_t& r3, uint32_t addr) {
    asm volatile("ldmatrix.sync.aligned.m8n8.x4.shared.b16 {%0,%1,%2,%3}, [%4];"
                 : "=r"(r0), "=r"(r1), "=r"(r2), "=r"(r3) : "r"(addr));
}
__device__ __forceinline__ void ldmatrix_x4_t(uint32_t& r0, uint32_t& r1,
                                              uint32_t& r2, uint32_t& r3, uint32_t addr) {
    asm volatile("ldmatrix.sync.aligned.m8n8.x4.trans.shared.b16 {%0,%1,%2,%3}, [%4];"
                 : "=r"(r0), "=r"(r1), "=r"(r2), "=r"(r3) : "r"(addr));
}
__device__ __forceinline__ void mma_bf16(float4& d, const uint32_t a[4],
                                         uint32_t b0, uint32_t b1) {
    asm volatile(
        "mma.sync.aligned.m16n8k16.row.col.f32.bf16.bf16.f32 "
        "{%0,%1,%2,%3},{%4,%5,%6,%7},{%8,%9},{%0,%1,%2,%3};"
        : "+f"(d.x), "+f"(d.y), "+f"(d.z), "+f"(d.w)
        : "r"(a[0]), "r"(a[1]), "r"(a[2]), "r"(a[3]), "r"(b0), "r"(b1));
}
__device__ __forceinline__ void mma_f16(float4& d, const uint32_t a[4],
                                        uint32_t b0, uint32_t b1) {
    asm volatile(
        "mma.sync.aligned.m16n8k16.row.col.f32.f16.f16.f32 "
        "{%0,%1,%2,%3},{%4,%5,%6,%7},{%8,%9},{%0,%1,%2,%3};"
        : "+f"(d.x), "+f"(d.y), "+f"(d.z), "+f"(d.w)
        : "r"(a[0]), "r"(a[1]), "r"(a[2]), "r"(a[3]), "r"(b0), "r"(b1));
}

// ---------------------------------------------------------------------------
// Kernel 0: split Q,K -> bf16 hi/lo; V -> fp16 hi/lo. [b,i,n,d] -> [b,n,i,d].
// ---------------------------------------------------------------------------
__global__ __launch_bounds__(256) void k_split(
    const float* __restrict__ q, const float* __restrict__ k,
    const float* __restrict__ v)
{
    int idx = blockIdx.x * 256 + threadIdx.x;   // BB*NH*LL*32
    int d2 = idx & 31;
    int j  = (idx >> 5) & (LL - 1);
    int n  = (idx >> 16) & 15;
    int b  = idx >> 20;
    size_t src = (((size_t)(b * LL + j)) * NH + n) * DD + d2 * 2;
    size_t dst = (((size_t)(b * NH + n)) * LL + j) * DD + d2 * 2;

    float2 xq = *(const float2*)&q[src];
    float2 xk = *(const float2*)&k[src];
    float2 xv = *(const float2*)&v[src];

    __nv_bfloat16 qh0 = __float2bfloat16_rn(xq.x), qh1 = __float2bfloat16_rn(xq.y);
    __nv_bfloat16 kh0 = __float2bfloat16_rn(xk.x), kh1 = __float2bfloat16_rn(xk.y);
    *(__nv_bfloat162*)&g_qh[dst] = __nv_bfloat162(qh0, qh1);
    *(__nv_bfloat162*)&g_kh[dst] = __nv_bfloat162(kh0, kh1);
    *(__nv_bfloat162*)&g_ql[dst] = __nv_bfloat162(
        __float2bfloat16_rn(xq.x - __bfloat162float(qh0)),
        __float2bfloat16_rn(xq.y - __bfloat162float(qh1)));
    *(__nv_bfloat162*)&g_kl[dst] = __nv_bfloat162(
        __float2bfloat16_rn(xk.x - __bfloat162float(kh0)),
        __float2bfloat16_rn(xk.y - __bfloat162float(kh1)));

    __half vh0 = __float2half_rn(xv.x), vh1 = __float2half_rn(xv.y);
    *(__half2*)&g_vh[dst] = __half2(vh0, vh1);
    *(__half2*)&g_vl[dst] = __half2(
        __float2half_rn(xv.x - __half2float(vh0)),
        __float2half_rn(xv.y - __half2float(vh1)));
}

// smem element offsets for k_scores (16-bit units)
#define QHI_OFF 0
#define QLO_OFF (TI * PCH)
#define KHI_OFF (2 * TI * PCH)
#define KLO_OFF (2 * TI * PCH + TJ * PCH)
#define MSK_OFF ((2 * TI * PCH + 2 * TJ * PCH) * 2)       // byte offset of mask
#define SMEM1_BYTES (MSK_OFF + TI * TJ)                   // 55296 + 8192 = 63488 B

// ---------------------------------------------------------------------------
// Kernel 1: HMMA scores (bf16x3). CTA = (b,n) x 128i x 64j, 8 warps, warp=16i.
// Mask prefetched to smem bytes. fp16 u output + per-warp row sums.
// ---------------------------------------------------------------------------
__global__ __launch_bounds__(256, 3) void k_scores(const int* __restrict__ mask)
{
    extern __shared__ __nv_bfloat16 sb[];
    unsigned char* Msk = (unsigned char*)sb + MSK_OFF;

    const int b  = blockIdx.x >> 4;
    const int n  = blockIdx.x & 15;
    const int j0 = blockIdx.y * TJ;
    const int jt = blockIdx.y;
    const int i0 = blockIdx.z * TI;
    const int tid  = threadIdx.x;
    const int w    = tid >> 5;
    const int lane = tid & 31;

    // ---- prefetch mask tile 128x64 -> packed bytes (issue first) ----
    const size_t mbase = (size_t)(b * LL + i0) * LL + j0;
#pragma unroll
    for (int t = 0; t < 8; t++) {
        int idx = tid + t * 256;           // 2048 int4
        int j4 = idx & 15, i = idx >> 4;
        int4 m = *(const int4*)&mask[mbase + (size_t)i * LL + j4 * 4];
        unsigned pack = (m.x ? 1u : 0u) | (m.y ? 0x100u : 0u) |
                        (m.z ? 0x10000u : 0u) | (m.w ? 0x1000000u : 0u);
        *(unsigned*)&Msk[i * 64 + j4 * 4] = pack;
    }

    // ---- stage pre-split tiles ----
    const size_t qbase = ((size_t)(b * NH + n) * LL + i0) * DD;
    const size_t kbase = ((size_t)(b * NH + n) * LL + j0) * DD;
#pragma unroll
    for (int t = 0; t < 4; t++) {
        int idx = tid + t * 256;           // 1024 uint4 per array
        int r = idx >> 3, c8 = idx & 7;
        int o = r * PCH + c8 * 8;
        size_t gq = qbase + (size_t)r * DD + c8 * 8;
        *(uint4*)&sb[QHI_OFF + o] = *(const uint4*)&g_qh[gq];
        *(uint4*)&sb[QLO_OFF + o] = *(const uint4*)&g_ql[gq];
    }
#pragma unroll
    for (int t = 0; t < 2; t++) {
        int idx = tid + t * 256;           // 512 uint4 per array
        int r = idx >> 3, c8 = idx & 7;
        int o = r * PCH + c8 * 8;
        size_t gk = kbase + (size_t)r * DD + c8 * 8;
        *(uint4*)&sb[KHI_OFF + o] = *(const uint4*)&g_kh[gk];
        *(uint4*)&sb[KLO_OFF + o] = *(const uint4*)&g_kl[gk];
    }
    __syncthreads();

    float4 acc[8];
#pragma unroll
    for (int jf = 0; jf < 8; jf++) acc[jf] = make_float4(0.f, 0.f, 0.f, 0.f);

    const int a_row = w * 16 + (lane & 15);
    const int a_kof = (lane >> 4) << 3;
    const int b_row = ((lane >> 4) << 3) + (lane & 7);
    const int b_kof = ((lane >> 3) & 1) << 3;

#pragma unroll
    for (int ks = 0; ks < 4; ks++) {
        const int k0 = ks * 16;
        uint32_t ah[4], al[4];
        ldmatrix_x4(ah[0], ah[1], ah[2], ah[3],
                    smem_u32(&sb[QHI_OFF + a_row * PCH + k0 + a_kof]));
        ldmatrix_x4(al[0], al[1], al[2], al[3],
                    smem_u32(&sb[QLO_OFF + a_row * PCH + k0 + a_kof]));
#pragma unroll
        for (int jp = 0; jp < 4; jp++) {
            uint32_t bh0, bh1, bh2, bh3, bl0, bl1, bl2, bl3;
            ldmatrix_x4(bh0, bh1, bh2, bh3,
                        smem_u32(&sb[KHI_OFF + (jp * 16 + b_row) * PCH + k0 + b_kof]));
            ldmatrix_x4(bl0, bl1, bl2, bl3,
                        smem_u32(&sb[KLO_OFF + (jp * 16 + b_row) * PCH + k0 + b_kof]));
            mma_bf16(acc[jp * 2],     ah, bh0, bh1);
            mma_bf16(acc[jp * 2],     ah, bl0, bl1);
            mma_bf16(acc[jp * 2],     al, bh0, bh1);
            mma_bf16(acc[jp * 2 + 1], ah, bh2, bh3);
            mma_bf16(acc[jp * 2 + 1], ah, bl2, bl3);
            mma_bf16(acc[jp * 2 + 1], al, bh2, bh3);
        }
    }

    // ---- epilogue: u = exp(s) (masked -> 0), fp16 store, per-warp row sums ----
    const int qr = lane >> 2, qc = (lane & 3) * 2;
    const int lr0 = w * 16 + qr;           // local row (second: +8)
    const int r0g = i0 + lr0;
    const size_t srow0 = ((size_t)(b * NH + n) * LL + r0g) * LL + j0;
    const size_t srow1 = srow0 + (size_t)8 * LL;
    float sum0 = 0.f, sum1 = 0.f;
#pragma unroll
    for (int jf = 0; jf < 8; jf++) {
        const int lj = jf * 8 + qc;
        float4 a = acc[jf];
        unsigned char m0a = Msk[lr0 * 64 + lj],       m0b = Msk[lr0 * 64 + lj + 1];
        unsigned char m1a = Msk[(lr0 + 8) * 64 + lj], m1b = Msk[(lr0 + 8) * 64 + lj + 1];
        float u0x = m0a ? 0.f : __expf(a.x * SCALE);
        float u0y = m0b ? 0.f : __expf(a.y * SCALE);
        float u1x = m1a ? 0.f : __expf(a.z * SCALE);
        float u1y = m1b ? 0.f : __expf(a.w * SCALE);
        *(__half2*)&g_scores[srow0 + lj] = __floats2half2_rn(u0x, u0y);
        *(__half2*)&g_scores[srow1 + lj] = __floats2half2_rn(u1x, u1y);
        sum0 += u0x + u0y;
        sum1 += u1x + u1y;
    }
    sum0 += __shfl_xor_sync(0xffffffffu, sum0, 1);
    sum0 += __shfl_xor_sync(0xffffffffu, sum0, 2);
    sum1 += __shfl_xor_sync(0xffffffffu, sum1, 1);
    sum1 += __shfl_xor_sync(0xffffffffu, sum1, 2);
    if ((lane & 3) == 0) {
        size_t base = (size_t)jt * NROWS + (size_t)(b * NH + n) * LL + r0g;
        g_tl[base] = sum0;
        g_tl[base + 8] = sum1;
    }
}

// ---------------------------------------------------------------------------
// Kernel 2: combine tile sums -> g_c = 1/L.
// ---------------------------------------------------------------------------
__global__ __launch_bounds__(256) void k_comb()
{
    const int r = blockIdx.x * 256 + threadIdx.x;
    float L = 0.f;
#pragma unroll
    for (int t = 0; t < NTJ; t++) L += g_tl[(size_t)t * NROWS + r];
    const int i = r & (LL - 1);
    const int n = (r >> 11) & (NH - 1);
    const int b = r >> 15;
    g_c[((size_t)(b * LL + i)) * NH + n] = 1.f / L;
}

// ---------------------------------------------------------------------------
// Kernel 3: attn output. p = u * c, transpose [b,n,i,j](fp16) -> [b,i,j,n](f32).
// CTA: 32i x 32j x 16n tile. S addr = jj*545 + ii*17 + n (fill conflict-free,
// read ~2-way); gmem writes are float4-coalesced.
// ---------------------------------------------------------------------------
#define RS 545
__global__ __launch_bounds__(256, 2) void k_attn(float* __restrict__ attn)
{
    extern __shared__ float S[];       // 32*RS floats
    __shared__ float Cs[512];          // [32 ii][16 n]
    const int b = blockIdx.z, i0 = blockIdx.y * 32, j0 = blockIdx.x * 32;
    const int tid = threadIdx.x;

    for (int t = tid; t < 512; t += 256)
        Cs[t] = g_c[(size_t)(b * LL + i0) * NH + t];
    __syncthreads();

#pragma unroll
    for (int kk = 0; kk < 8; kk++) {
        int idx = tid + kk * 256;          // 2048 uint4 (8 halves each)
        int c8 = idx & 3, ii = (idx >> 2) & 31, n = idx >> 7;
        uint4 raw = *(const uint4*)&g_scores[
            (((size_t)(b * NH + n)) * LL + i0 + ii) * LL + j0 + c8 * 8];
        const __half2* h2 = (const __half2*)&raw;
        float c = Cs[ii * 16 + n];
        int sbase = ii * 17 + n;
#pragma unroll
        for (int t = 0; t < 4; t++) {
            float2 f = __half22float2(h2[t]);
            int jl = c8 * 8 + t * 2;
            S[jl * RS + sbase] = f.x * c;
            S[(jl + 1) * RS + sbase] = f.y * c;
        }
    }
    __syncthreads();

#pragma unroll
    for (int kk = 0; kk < 16; kk++) {
        int idx = tid + kk * 256;          // 4096 float4
        int n4 = (idx & 3) * 4, jj = (idx >> 2) & 31, ii = idx >> 7;
        const float* s = &S[jj * RS + ii * 17 + n4];
        float4 v = make_float4(s[0], s[1], s[2], s[3]);
        *(float4*)&attn[(((size_t)(b * LL + i0 + ii)) * LL + j0 + jj) * NH + n4] = v;
    }
}

// ---------------------------------------------------------------------------
// Kernel 4: tensor PV on raw fp16 u (normalization deferred to epilogue).
// CTA = (b,n) x 128 i. 8 warps, warp = 16 i x 64 d. ctx = c * (P_f16 @ (Vhi+Vlo)).
// ---------------------------------------------------------------------------
#define PVH_OFF 0
#define VVH_OFF (128 * PCH)
#define VVL_OFF (128 * PCH + 64 * PCH)
#define SMEM4_BYTES ((128 * PCH + 2 * 64 * PCH) * 2)  // 36864 B

__global__ __launch_bounds__(256, 3) void k_pvt(float* __restrict__ ctx)
{
    extern __shared__ __half pb[];

    const int bn = blockIdx.x;           // b*16+n
    const int b = bn >> 4, n = bn & 15;
    const int i0 = blockIdx.y * 128;
    const int tid = threadIdx.x, w = tid >> 5, lane = tid & 31;

    float4 acc[8];
#pragma unroll
    for (int g = 0; g < 8; g++) acc[g] = make_float4(0.f, 0.f, 0.f, 0.f);

    const size_t ubase = ((size_t)bn * LL + i0) * LL;
    const size_t vbase = (size_t)bn * LL * DD;

    const int a_row = w * 16 + (lane & 15);
    const int a_kof = (lane >> 4) << 3;
    const int v_rof = ((lane >> 3) & 1) * 8 + (lane & 7);
    const int v_cof = (lane >> 4) * 8;

    for (int j0 = 0; j0 < LL; j0 += 64) {
        for (int t = tid; t < 512; t += 256) {
            int r = t >> 3, c8 = t & 7;
            size_t gv = vbase + (size_t)(j0 + r) * DD + c8 * 8;
            *(uint4*)&pb[VVH_OFF + r * PCH + c8 * 8] = *(const uint4*)&g_vh[gv];
            *(uint4*)&pb[VVL_OFF + r * PCH + c8 * 8] = *(const uint4*)&g_vl[gv];
        }
#pragma unroll
        for (int t = 0; t < 4; t++) {
            int idx = tid + t * 256;       // 1024 uint4
            int row = idx >> 3, c8 = idx & 7;
            *(uint4*)&pb[PVH_OFF + row * PCH + c8 * 8] =
                *(const uint4*)&g_scores[ubase + (size_t)row * LL + j0 + c8 * 8];
        }
        __syncthreads();

#pragma unroll
        for (int ks = 0; ks < 4; ks++) {
            const int k0 = ks * 16;
            uint32_t ah[4];
            ldmatrix_x4(ah[0], ah[1], ah[2], ah[3],
                        smem_u32(&pb[PVH_OFF + a_row * PCH + k0 + a_kof]));
#pragma unroll
            for (int ng = 0; ng < 4; ng++) {
                uint32_t bh0, bh1, bh2, bh3, bl0, bl1, bl2, bl3;
                const int voff = (k0 + v_rof) * PCH + ng * 16 + v_cof;
                ldmatrix_x4_t(bh0, bh1, bh2, bh3, smem_u32(&pb[VVH_OFF + voff]));
                ldmatrix_x4_t(bl0, bl1, bl2, bl3, smem_u32(&pb[VVL_OFF + voff]));
                mma_f16(acc[ng * 2],     ah, bh0, bh1);
                mma_f16(acc[ng * 2],     ah, bl0, bl1);
                mma_f16(acc[ng * 2 + 1], ah, bh2, bh3);
                mma_f16(acc[ng * 2 + 1], ah, bl2, bl3);
            }
        }
        __syncthreads();
    }

    const int r = w * 16 + (lane >> 2);
    const float c0 = g_c[((size_t)(b * LL + i0 + r)) * NH + n];
    const float c1 = g_c[((size_t)(b * LL + i0 + r + 8)) * NH + n];
#pragma unroll
    for (int ng = 0; ng < 8; ng++) {
        int colb = ng * 8 + (lane & 3) * 2;
        size_t g0 = (((size_t)(b * LL + i0 + r)) * NH + n) * DD + colb;
        size_t g1 = (((size_t)(b * LL + i0 + r + 8)) * NH + n) * DD + colb;
        *(float2*)&ctx[g0] = make_float2(acc[ng].x * c0, acc[ng].y * c0);
        *(float2*)&ctx[g1] = make_float2(acc[ng].z * c1, acc[ng].w * c1);
    }
}

// ---------------------------------------------------------------------------
extern "C" void kernel_launch(void* const* d_in, const int* in_sizes, int n_in,
                              void* d_out, int out_size)
{
    const float* q = (const float*)d_in[0];
    const float* k = (const float*)d_in[1];
    const float* v = (const float*)d_in[2];
    const int* mask = (const int*)d_in[3];

    float* ctx  = (float*)d_out;
    float* attn = (float*)d_out + (size_t)BB * LL * NH * DD;

    const int smem_attn = 32 * RS * 4;          // 69760 B
    cudaFuncSetAttribute(k_scores, cudaFuncAttributeMaxDynamicSharedMemorySize, SMEM1_BYTES);
    cudaFuncSetAttribute(k_attn,   cudaFuncAttributeMaxDynamicSharedMemorySize, smem_attn);

    k_split<<<(BB * NH * LL * 32) / 256, 256>>>(q, k, v);

    dim3 g1(BB * NH, LL / TJ, LL / TI);
    k_scores<<<g1, 256, SMEM1_BYTES>>>(mask);

    k_comb<<<NROWS / 256, 256>>>();

    dim3 ga(LL / 32, LL / 32, BB);
    k_attn<<<ga, 256, smem_attn>>>(attn);

    dim3 gp(BB * NH, LL / 128);
    k_pvt<<<gp, 256, SMEM4_BYTES>>>(ctx);
}

// round 11
// speedup vs baseline: 4.0982x; 1.2115x over previous
#include <cuda_runtime.h>
#include <cuda_bf16.h>
#include <cuda_fp16.h>
#include <math_constants.h>
#include <cstdint>

#define BB 2
#define LL 2048
#define NH 16
#define DD 64
#define SCALE 0.125f

#define TI 128
#define TJ 64
#define NTJ (LL / TJ)            // 32 j-tiles
#define NROWS (BB * NH * LL)     // 65536 softmax rows
#define PCH 72                   // smem pitch in 16-bit elems (144B rows -> conflict-free LDSM)

// scores scratch: u = exp(masked scaled score) in fp16, layout [b][n][i][j]
__device__ __half g_scores[(size_t)BB * NH * LL * LL];
// per-(row, j-tile) partial sums of u, layout [jt][b][n][i]
__device__ float g_tl[NTJ * NROWS];
// final per-row 1/sum, layout [b][i][n]
__device__ float g_c[BB * LL * NH];
// pre-split Q/K (bf16 hi/lo) and V (fp16 hi/lo), layout [b][n][j][d]
__device__ __nv_bfloat16 g_qh[(size_t)BB * NH * LL * DD];
__device__ __nv_bfloat16 g_ql[(size_t)BB * NH * LL * DD];
__device__ __nv_bfloat16 g_kh[(size_t)BB * NH * LL * DD];
__device__ __nv_bfloat16 g_kl[(size_t)BB * NH * LL * DD];
__device__ __half g_vh[(size_t)BB * NH * LL * DD];
__device__ __half g_vl[(size_t)BB * NH * LL * DD];

// ---------------- portable tensor helpers (sm_80+) ----------------
__device__ __forceinline__ uint32_t smem_u32(const void* p) {
    uint32_t a;
    asm("{ .reg .u64 t; cvta.to.shared.u64 t, %1; cvt.u32.u64 %0, t; }" : "=r"(a) : "l"(p));
    return a;
}
__device__ __forceinline__ void ldmatrix_x4(uint32_t& r0, uint32_t& r1,
                                            uint32_t& r2, uint32_t& r3, uint32_t addr) {
    asm volatile("ldmatrix.sync.aligned.m8n8.x4.shared.b16 {%0,%1,%2,%3}, [%4];"
                 : "=r"(r0), "=r"(r1), "=r"(r2), "=r"(r3) : "r"(addr));
}
__device__ __forceinline__ void ldmatrix_x4_t(uint32_t& r0, uint32_t& r1,
                                              uint32_t& r2, uint32_t& r3, uint32_t addr) {
    asm volatile("ldmatrix.sync.aligned.m8n8.x4.trans.shared.b16 {%0,%1,%2,%3}, [%4];"
                 : "=r"(r0), "=r"(r1), "=r"(r2), "=r"(r3) : "r"(addr));
}
__device__ __forceinline__ void mma_bf16(float4& d, const uint32_t a[4],
                                         uint32_t b0, uint32_t b1) {
    asm volatile(
        "mma.sync.aligned.m16n8k16.row.col.f32.bf16.bf16.f32 "
        "{%0,%1,%2,%3},{%4,%5,%6,%7},{%8,%9},{%0,%1,%2,%3};"
        : "+f"(d.x), "+f"(d.y), "+f"(d.z), "+f"(d.w)
        : "r"(a[0]), "r"(a[1]), "r"(a[2]), "r"(a[3]), "r"(b0), "r"(b1));
}
__device__ __forceinline__ void mma_f16(float4& d, const uint32_t a[4],
                                        uint32_t b0, uint32_t b1) {
    asm volatile(
        "mma.sync.aligned.m16n8k16.row.col.f32.f16.f16.f32 "
        "{%0,%1,%2,%3},{%4,%5,%6,%7},{%8,%9},{%0,%1,%2,%3};"
        : "+f"(d.x), "+f"(d.y), "+f"(d.z), "+f"(d.w)
        : "r"(a[0]), "r"(a[1]), "r"(a[2]), "r"(a[3]), "r"(b0), "r"(b1));
}
__device__ __forceinline__ void cp_async16(uint32_t smem, const void* gmem) {
    asm volatile("cp.async.cg.shared.global [%0], [%1], 16;" :: "r"(smem), "l"(gmem));
}
#define CP_COMMIT() asm volatile("cp.async.commit_group;" ::: "memory")
#define CP_WAIT(n)  asm volatile("cp.async.wait_group %0;" :: "n"(n) : "memory")

// ---------------------------------------------------------------------------
// Kernel 0: split Q,K -> bf16 hi/lo; V -> fp16 hi/lo. [b,i,n,d] -> [b,n,i,d].
// ---------------------------------------------------------------------------
__global__ __launch_bounds__(256) void k_split(
    const float* __restrict__ q, const float* __restrict__ k,
    const float* __restrict__ v)
{
    int idx = blockIdx.x * 256 + threadIdx.x;   // BB*NH*LL*32
    int d2 = idx & 31;
    int j  = (idx >> 5) & (LL - 1);
    int n  = (idx >> 16) & 15;
    int b  = idx >> 20;
    size_t src = (((size_t)(b * LL + j)) * NH + n) * DD + d2 * 2;
    size_t dst = (((size_t)(b * NH + n)) * LL + j) * DD + d2 * 2;

    float2 xq = *(const float2*)&q[src];
    float2 xk = *(const float2*)&k[src];
    float2 xv = *(const float2*)&v[src];

    __nv_bfloat16 qh0 = __float2bfloat16_rn(xq.x), qh1 = __float2bfloat16_rn(xq.y);
    __nv_bfloat16 kh0 = __float2bfloat16_rn(xk.x), kh1 = __float2bfloat16_rn(xk.y);
    *(__nv_bfloat162*)&g_qh[dst] = __nv_bfloat162(qh0, qh1);
    *(__nv_bfloat162*)&g_kh[dst] = __nv_bfloat162(kh0, kh1);
    *(__nv_bfloat162*)&g_ql[dst] = __nv_bfloat162(
        __float2bfloat16_rn(xq.x - __bfloat162float(qh0)),
        __float2bfloat16_rn(xq.y - __bfloat162float(qh1)));
    *(__nv_bfloat162*)&g_kl[dst] = __nv_bfloat162(
        __float2bfloat16_rn(xk.x - __bfloat162float(kh0)),
        __float2bfloat16_rn(xk.y - __bfloat162float(kh1)));

    __half vh0 = __float2half_rn(xv.x), vh1 = __float2half_rn(xv.y);
    *(__half2*)&g_vh[dst] = __half2(vh0, vh1);
    *(__half2*)&g_vl[dst] = __half2(
        __float2half_rn(xv.x - __half2float(vh0)),
        __float2half_rn(xv.y - __half2float(vh1)));
}

// smem element offsets for k_scores (16-bit units)
#define QHI_OFF 0
#define QLO_OFF (TI * PCH)
#define KHI_OFF (2 * TI * PCH)
#define KLO_OFF (2 * TI * PCH + TJ * PCH)
#define MSK_OFF ((2 * TI * PCH + 2 * TJ * PCH) * 2)       // byte offset of mask
#define SMEM1_BYTES (MSK_OFF + TI * TJ)                   // 55296 + 8192 = 63488 B

// ---------------------------------------------------------------------------
// Kernel 1: HMMA scores (bf16x3). CTA = (b,n) x 128i x 64j, 8 warps, warp=16i.
// ---------------------------------------------------------------------------
__global__ __launch_bounds__(256, 3) void k_scores(const int* __restrict__ mask)
{
    extern __shared__ __nv_bfloat16 sb[];
    unsigned char* Msk = (unsigned char*)sb + MSK_OFF;

    const int b  = blockIdx.x >> 4;
    const int n  = blockIdx.x & 15;
    const int j0 = blockIdx.y * TJ;
    const int jt = blockIdx.y;
    const int i0 = blockIdx.z * TI;
    const int tid  = threadIdx.x;
    const int w    = tid >> 5;
    const int lane = tid & 31;

    const size_t mbase = (size_t)(b * LL + i0) * LL + j0;
#pragma unroll
    for (int t = 0; t < 8; t++) {
        int idx = tid + t * 256;           // 2048 int4
        int j4 = idx & 15, i = idx >> 4;
        int4 m = *(const int4*)&mask[mbase + (size_t)i * LL + j4 * 4];
        unsigned pack = (m.x ? 1u : 0u) | (m.y ? 0x100u : 0u) |
                        (m.z ? 0x10000u : 0u) | (m.w ? 0x1000000u : 0u);
        *(unsigned*)&Msk[i * 64 + j4 * 4] = pack;
    }

    const size_t qbase = ((size_t)(b * NH + n) * LL + i0) * DD;
    const size_t kbase = ((size_t)(b * NH + n) * LL + j0) * DD;
#pragma unroll
    for (int t = 0; t < 4; t++) {
        int idx = tid + t * 256;
        int r = idx >> 3, c8 = idx & 7;
        int o = r * PCH + c8 * 8;
        size_t gq = qbase + (size_t)r * DD + c8 * 8;
        *(uint4*)&sb[QHI_OFF + o] = *(const uint4*)&g_qh[gq];
        *(uint4*)&sb[QLO_OFF + o] = *(const uint4*)&g_ql[gq];
    }
#pragma unroll
    for (int t = 0; t < 2; t++) {
        int idx = tid + t * 256;
        int r = idx >> 3, c8 = idx & 7;
        int o = r * PCH + c8 * 8;
        size_t gk = kbase + (size_t)r * DD + c8 * 8;
        *(uint4*)&sb[KHI_OFF + o] = *(const uint4*)&g_kh[gk];
        *(uint4*)&sb[KLO_OFF + o] = *(const uint4*)&g_kl[gk];
    }
    __syncthreads();

    float4 acc[8];
#pragma unroll
    for (int jf = 0; jf < 8; jf++) acc[jf] = make_float4(0.f, 0.f, 0.f, 0.f);

    const int a_row = w * 16 + (lane & 15);
    const int a_kof = (lane >> 4) << 3;
    const int b_row = ((lane >> 4) << 3) + (lane & 7);
    const int b_kof = ((lane >> 3) & 1) << 3;

#pragma unroll
    for (int ks = 0; ks < 4; ks++) {
        const int k0 = ks * 16;
        uint32_t ah[4], al[4];
        ldmatrix_x4(ah[0], ah[1], ah[2], ah[3],
                    smem_u32(&sb[QHI_OFF + a_row * PCH + k0 + a_kof]));
        ldmatrix_x4(al[0], al[1], al[2], al[3],
                    smem_u32(&sb[QLO_OFF + a_row * PCH + k0 + a_kof]));
#pragma unroll
        for (int jp = 0; jp < 4; jp++) {
            uint32_t bh0, bh1, bh2, bh3, bl0, bl1, bl2, bl3;
            ldmatrix_x4(bh0, bh1, bh2, bh3,
                        smem_u32(&sb[KHI_OFF + (jp * 16 + b_row) * PCH + k0 + b_kof]));
            ldmatrix_x4(bl0, bl1, bl2, bl3,
                        smem_u32(&sb[KLO_OFF + (jp * 16 + b_row) * PCH + k0 + b_kof]));
            mma_bf16(acc[jp * 2],     ah, bh0, bh1);
            mma_bf16(acc[jp * 2],     ah, bl0, bl1);
            mma_bf16(acc[jp * 2],     al, bh0, bh1);
            mma_bf16(acc[jp * 2 + 1], ah, bh2, bh3);
            mma_bf16(acc[jp * 2 + 1], ah, bl2, bl3);
            mma_bf16(acc[jp * 2 + 1], al, bh2, bh3);
        }
    }

    const int qr = lane >> 2, qc = (lane & 3) * 2;
    const int lr0 = w * 16 + qr;
    const int r0g = i0 + lr0;
    const size_t srow0 = ((size_t)(b * NH + n) * LL + r0g) * LL + j0;
    const size_t srow1 = srow0 + (size_t)8 * LL;
    float sum0 = 0.f, sum1 = 0.f;
#pragma unroll
    for (int jf = 0; jf < 8; jf++) {
        const int lj = jf * 8 + qc;
        float4 a = acc[jf];
        unsigned char m0a = Msk[lr0 * 64 + lj],       m0b = Msk[lr0 * 64 + lj + 1];
        unsigned char m1a = Msk[(lr0 + 8) * 64 + lj], m1b = Msk[(lr0 + 8) * 64 + lj + 1];
        float u0x = m0a ? 0.f : __expf(a.x * SCALE);
        float u0y = m0b ? 0.f : __expf(a.y * SCALE);
        float u1x = m1a ? 0.f : __expf(a.z * SCALE);
        float u1y = m1b ? 0.f : __expf(a.w * SCALE);
        *(__half2*)&g_scores[srow0 + lj] = __floats2half2_rn(u0x, u0y);
        *(__half2*)&g_scores[srow1 + lj] = __floats2half2_rn(u1x, u1y);
        sum0 += u0x + u0y;
        sum1 += u1x + u1y;
    }
    sum0 += __shfl_xor_sync(0xffffffffu, sum0, 1);
    sum0 += __shfl_xor_sync(0xffffffffu, sum0, 2);
    sum1 += __shfl_xor_sync(0xffffffffu, sum1, 1);
    sum1 += __shfl_xor_sync(0xffffffffu, sum1, 2);
    if ((lane & 3) == 0) {
        size_t base = (size_t)jt * NROWS + (size_t)(b * NH + n) * LL + r0g;
        g_tl[base] = sum0;
        g_tl[base + 8] = sum1;
    }
}

// ---------------------------------------------------------------------------
// Kernel 2: combine tile sums -> g_c = 1/L.
// ---------------------------------------------------------------------------
__global__ __launch_bounds__(256) void k_comb()
{
    const int r = blockIdx.x * 256 + threadIdx.x;
    float L = 0.f;
#pragma unroll
    for (int t = 0; t < NTJ; t++) L += g_tl[(size_t)t * NROWS + r];
    const int i = r & (LL - 1);
    const int n = (r >> 11) & (NH - 1);
    const int b = r >> 15;
    g_c[((size_t)(b * LL + i)) * NH + n] = 1.f / L;
}

// ---------------------------------------------------------------------------
// Kernel 3: attn output. 512 threads for latency hiding (32 warps/SM @ 2 CTA).
// p = u * c, transpose [b,n,i,j](fp16) -> [b,i,j,n](f32). 32i x 32j x 16n tile.
// ---------------------------------------------------------------------------
#define RS 545
__global__ __launch_bounds__(512, 2) void k_attn(float* __restrict__ attn)
{
    extern __shared__ float S[];       // 32*RS floats
    __shared__ float Cs[512];          // [32 ii][16 n]
    const int b = blockIdx.z, i0 = blockIdx.y * 32, j0 = blockIdx.x * 32;
    const int tid = threadIdx.x;

    Cs[tid] = g_c[(size_t)(b * LL + i0) * NH + tid];
    __syncthreads();

#pragma unroll
    for (int kk = 0; kk < 4; kk++) {
        int idx = tid + kk * 512;          // 2048 uint4 (8 halves each)
        int c8 = idx & 3, ii = (idx >> 2) & 31, n = idx >> 7;
        uint4 raw = *(const uint4*)&g_scores[
            (((size_t)(b * NH + n)) * LL + i0 + ii) * LL + j0 + c8 * 8];
        const __half2* h2 = (const __half2*)&raw;
        float c = Cs[ii * 16 + n];
        int sbase = ii * 17 + n;
#pragma unroll
        for (int t = 0; t < 4; t++) {
            float2 f = __half22float2(h2[t]);
            int jl = c8 * 8 + t * 2;
            S[jl * RS + sbase] = f.x * c;
            S[(jl + 1) * RS + sbase] = f.y * c;
        }
    }
    __syncthreads();

#pragma unroll
    for (int kk = 0; kk < 8; kk++) {
        int idx = tid + kk * 512;          // 4096 float4
        int n4 = (idx & 3) * 4, jj = (idx >> 2) & 31, ii = idx >> 7;
        const float* s = &S[jj * RS + ii * 17 + n4];
        float4 v = make_float4(s[0], s[1], s[2], s[3]);
        *(float4*)&attn[(((size_t)(b * LL + i0 + ii)) * LL + j0 + jj) * NH + n4] = v;
    }
}

// ---------------------------------------------------------------------------
// Kernel 4: tensor PV, cp.async double-buffered.
// CTA = (b,n) x 128 i. 8 warps, warp = 16 i x 64 d. ctx = c * (P_f16 @ (Vhi+Vlo)).
// ---------------------------------------------------------------------------
#define PVB_L 0
#define VVH_L (128 * PCH)
#define VVL_L (128 * PCH + 64 * PCH)
#define ST_ELEMS (128 * PCH + 2 * 64 * PCH)     // 18432 halves / stage
#define SMEM4_BYTES (2 * ST_ELEMS * 2)          // 73728 B

__global__ __launch_bounds__(256, 3) void k_pvt(float* __restrict__ ctx)
{
    extern __shared__ __half pb[];

    const int bn = blockIdx.x;           // b*16+n
    const int b = bn >> 4, n = bn & 15;
    const int i0 = blockIdx.y * 128;
    const int tid = threadIdx.x, w = tid >> 5, lane = tid & 31;

    float4 acc[8];
#pragma unroll
    for (int g = 0; g < 8; g++) acc[g] = make_float4(0.f, 0.f, 0.f, 0.f);

    const size_t ubase = ((size_t)bn * LL + i0) * LL;
    const size_t vbase = (size_t)bn * LL * DD;
    const uint32_t pb0 = smem_u32(pb);

    const int a_row = w * 16 + (lane & 15);
    const int a_kof = (lane >> 4) << 3;
    const int v_rof = ((lane >> 3) & 1) * 8 + (lane & 7);
    const int v_cof = (lane >> 4) * 8;

    // async stage loader: V hi/lo [64 j][64 d] + u [128 i][64 j]
    auto issue = [&](int jt, int stage) {
        const uint32_t dst = pb0 + stage * (ST_ELEMS * 2);
        const int j0 = jt * 64;
#pragma unroll
        for (int t = 0; t < 2; t++) {
            int idx = tid + t * 256;       // 512 lines per V array
            int r = idx >> 3, c8 = idx & 7;
            size_t gv = vbase + (size_t)(j0 + r) * DD + c8 * 8;
            cp_async16(dst + (VVH_L + r * PCH + c8 * 8) * 2, &g_vh[gv]);
            cp_async16(dst + (VVL_L + r * PCH + c8 * 8) * 2, &g_vl[gv]);
        }
#pragma unroll
        for (int t = 0; t < 4; t++) {
            int idx = tid + t * 256;       // 1024 lines for u
            int row = idx >> 3, c8 = idx & 7;
            cp_async16(dst + (PVB_L + row * PCH + c8 * 8) * 2,
                       &g_scores[ubase + (size_t)row * LL + j0 + c8 * 8]);
        }
        CP_COMMIT();
    };

    issue(0, 0);

    for (int jt = 0; jt < NTJ; jt++) {
        const int cur = jt & 1;
        if (jt + 1 < NTJ) {
            issue(jt + 1, cur ^ 1);
            CP_WAIT(1);
        } else {
            CP_WAIT(0);
        }
        __syncthreads();

        const __half* buf = pb + cur * ST_ELEMS;
#pragma unroll
        for (int ks = 0; ks < 4; ks++) {
            const int k0 = ks * 16;
            uint32_t ah[4];
            ldmatrix_x4(ah[0], ah[1], ah[2], ah[3],
                        smem_u32(&buf[PVB_L + a_row * PCH + k0 + a_kof]));
#pragma unroll
            for (int ng = 0; ng < 4; ng++) {
                uint32_t bh0, bh1, bh2, bh3, bl0, bl1, bl2, bl3;
                const int voff = (k0 + v_rof) * PCH + ng * 16 + v_cof;
                ldmatrix_x4_t(bh0, bh1, bh2, bh3, smem_u32(&buf[VVH_L + voff]));
                ldmatrix_x4_t(bl0, bl1, bl2, bl3, smem_u32(&buf[VVL_L + voff]));
                mma_f16(acc[ng * 2],     ah, bh0, bh1);
                mma_f16(acc[ng * 2],     ah, bl0, bl1);
                mma_f16(acc[ng * 2 + 1], ah, bh2, bh3);
                mma_f16(acc[ng * 2 + 1], ah, bl2, bl3);
            }
        }
        __syncthreads();
    }

    const int r = w * 16 + (lane >> 2);
    const float c0 = g_c[((size_t)(b * LL + i0 + r)) * NH + n];
    const float c1 = g_c[((size_t)(b * LL + i0 + r + 8)) * NH + n];
#pragma unroll
    for (int ng = 0; ng < 8; ng++) {
        int colb = ng * 8 + (lane & 3) * 2;
        size_t g0 = (((size_t)(b * LL + i0 + r)) * NH + n) * DD + colb;
        size_t g1 = (((size_t)(b * LL + i0 + r + 8)) * NH + n) * DD + colb;
        *(float2*)&ctx[g0] = make_float2(acc[ng].x * c0, acc[ng].y * c0);
        *(float2*)&ctx[g1] = make_float2(acc[ng].z * c1, acc[ng].w * c1);
    }
}

// ---------------------------------------------------------------------------
extern "C" void kernel_launch(void* const* d_in, const int* in_sizes, int n_in,
                              void* d_out, int out_size)
{
    const float* q = (const float*)d_in[0];
    const float* k = (const float*)d_in[1];
    const float* v = (const float*)d_in[2];
    const int* mask = (const int*)d_in[3];

    float* ctx  = (float*)d_out;
    float* attn = (float*)d_out + (size_t)BB * LL * NH * DD;

    const int smem_attn = 32 * RS * 4;          // 69760 B
    cudaFuncSetAttribute(k_scores, cudaFuncAttributeMaxDynamicSharedMemorySize, SMEM1_BYTES);
    cudaFuncSetAttribute(k_attn,   cudaFuncAttributeMaxDynamicSharedMemorySize, smem_attn);
    cudaFuncSetAttribute(k_pvt,    cudaFuncAttributeMaxDynamicSharedMemorySize, SMEM4_BYTES);

    k_split<<<(BB * NH * LL * 32) / 256, 256>>>(q, k, v);

    dim3 g1(BB * NH, LL / TJ, LL / TI);
    k_scores<<<g1, 256, SMEM1_BYTES>>>(mask);

    k_comb<<<NROWS / 256, 256>>>();

    dim3 ga(LL / 32, LL / 32, BB);
    k_attn<<<ga, 512, smem_attn>>>(attn);

    dim3 gp(BB * NH, LL / 128);
    k_pvt<<<gp, 256, SMEM4_BYTES>>>(ctx);
}

// round 12
// speedup vs baseline: 4.7287x; 1.1539x over previous
#include <cuda_runtime.h>
#include <cuda_bf16.h>
#include <cuda_fp16.h>
#include <math_constants.h>
#include <cstdint>

#define BB 2
#define LL 2048
#define NH 16
#define DD 64
#define SCALE 0.125f

#define TI 128
#define TJ 64
#define NTJ (LL / TJ)            // 32 j-tiles
#define NROWS (BB * NH * LL)     // 65536 softmax rows
#define PCH 72                   // smem pitch in 16-bit elems (144B rows -> conflict-free LDSM)

// scores scratch: u = exp(masked scaled score) in fp16, layout [b][n][i][j]
__device__ __half g_scores[(size_t)BB * NH * LL * LL];
// per-(row, j-tile) partial sums of u, layout [jt][b][n][i]
__device__ float g_tl[NTJ * NROWS];
// final per-row 1/sum, layout [b][i][n]
__device__ float g_c[BB * LL * NH];
// pre-split operands (fp16), layout [b][n][j][d]
__device__ __half g_qh[(size_t)BB * NH * LL * DD];
__device__ __half g_ql[(size_t)BB * NH * LL * DD];
__device__ __half g_kh[(size_t)BB * NH * LL * DD];
__device__ __half g_vh[(size_t)BB * NH * LL * DD];

// ---------------- portable tensor helpers (sm_80+) ----------------
__device__ __forceinline__ uint32_t smem_u32(const void* p) {
    uint32_t a;
    asm("{ .reg .u64 t; cvta.to.shared.u64 t, %1; cvt.u32.u64 %0, t; }" : "=r"(a) : "l"(p));
    return a;
}
__device__ __forceinline__ void ldmatrix_x4(uint32_t& r0, uint32_t& r1,
                                            uint32_t& r2, uint32_t& r3, uint32_t addr) {
    asm volatile("ldmatrix.sync.aligned.m8n8.x4.shared.b16 {%0,%1,%2,%3}, [%4];"
                 : "=r"(r0), "=r"(r1), "=r"(r2), "=r"(r3) : "r"(addr));
}
__device__ __forceinline__ void ldmatrix_x4_t(uint32_t& r0, uint32_t& r1,
                                              uint32_t& r2, uint32_t& r3, uint32_t addr) {
    asm volatile("ldmatrix.sync.aligned.m8n8.x4.trans.shared.b16 {%0,%1,%2,%3}, [%4];"
                 : "=r"(r0), "=r"(r1), "=r"(r2), "=r"(r3) : "r"(addr));
}
__device__ __forceinline__ void mma_f16(float4& d, const uint32_t a[4],
                                        uint32_t b0, uint32_t b1) {
    asm volatile(
        "mma.sync.aligned.m16n8k16.row.col.f32.f16.f16.f32 "
        "{%0,%1,%2,%3},{%4,%5,%6,%7},{%8,%9},{%0,%1,%2,%3};"
        : "+f"(d.x), "+f"(d.y), "+f"(d.z), "+f"(d.w)
        : "r"(a[0]), "r"(a[1]), "r"(a[2]), "r"(a[3]), "r"(b0), "r"(b1));
}
__device__ __forceinline__ void cp_async16(uint32_t smem, const void* gmem) {
    asm volatile("cp.async.cg.shared.global [%0], [%1], 16;" :: "r"(smem), "l"(gmem));
}
#define CP_COMMIT() asm volatile("cp.async.commit_group;" ::: "memory")
#define CP_WAIT(n)  asm volatile("cp.async.wait_group %0;" :: "n"(n) : "memory")

// ---------------------------------------------------------------------------
// Kernel 0: split Q -> fp16 hi/lo; K,V -> fp16. [b,i,n,d] -> [b,n,i,d].
// ---------------------------------------------------------------------------
__global__ __launch_bounds__(256) void k_split(
    const float* __restrict__ q, const float* __restrict__ k,
    const float* __restrict__ v)
{
    int idx = blockIdx.x * 256 + threadIdx.x;   // BB*NH*LL*32
    int d2 = idx & 31;
    int j  = (idx >> 5) & (LL - 1);
    int n  = (idx >> 16) & 15;
    int b  = idx >> 20;
    size_t src = (((size_t)(b * LL + j)) * NH + n) * DD + d2 * 2;
    size_t dst = (((size_t)(b * NH + n)) * LL + j) * DD + d2 * 2;

    float2 xq = *(const float2*)&q[src];
    float2 xk = *(const float2*)&k[src];
    float2 xv = *(const float2*)&v[src];

    __half qh0 = __float2half_rn(xq.x), qh1 = __float2half_rn(xq.y);
    *(__half2*)&g_qh[dst] = __half2(qh0, qh1);
    *(__half2*)&g_ql[dst] = __half2(
        __float2half_rn(xq.x - __half2float(qh0)),
        __float2half_rn(xq.y - __half2float(qh1)));
    *(__half2*)&g_kh[dst] = __floats2half2_rn(xk.x, xk.y);
    *(__half2*)&g_vh[dst] = __floats2half2_rn(xv.x, xv.y);
}

// smem element offsets for k_scores (16-bit units)
#define QHI_OFF 0
#define QLO_OFF (TI * PCH)
#define KHI_OFF (2 * TI * PCH)
#define MSK_OFF ((2 * TI * PCH + TJ * PCH) * 2)           // byte offset of mask
#define SMEM1_BYTES (MSK_OFF + TI * TJ)                   // 46080 + 8192 = 54272 B

// ---------------------------------------------------------------------------
// Kernel 1: HMMA scores (fp16x2: S = (Qh+Ql)*Kh). CTA = (b,n) x 128i x 64j.
// 8 warps, warp = 16i x 64j. Mask prefetched to smem bytes.
// ---------------------------------------------------------------------------
__global__ __launch_bounds__(256, 3) void k_scores(const int* __restrict__ mask)
{
    extern __shared__ __half sb[];
    unsigned char* Msk = (unsigned char*)sb + MSK_OFF;

    const int b  = blockIdx.x >> 4;
    const int n  = blockIdx.x & 15;
    const int j0 = blockIdx.y * TJ;
    const int jt = blockIdx.y;
    const int i0 = blockIdx.z * TI;
    const int tid  = threadIdx.x;
    const int w    = tid >> 5;
    const int lane = tid & 31;

    const size_t mbase = (size_t)(b * LL + i0) * LL + j0;
#pragma unroll
    for (int t = 0; t < 8; t++) {
        int idx = tid + t * 256;           // 2048 int4
        int j4 = idx & 15, i = idx >> 4;
        int4 m = *(const int4*)&mask[mbase + (size_t)i * LL + j4 * 4];
        unsigned pack = (m.x ? 1u : 0u) | (m.y ? 0x100u : 0u) |
                        (m.z ? 0x10000u : 0u) | (m.w ? 0x1000000u : 0u);
        *(unsigned*)&Msk[i * 64 + j4 * 4] = pack;
    }

    const size_t qbase = ((size_t)(b * NH + n) * LL + i0) * DD;
    const size_t kbase = ((size_t)(b * NH + n) * LL + j0) * DD;
#pragma unroll
    for (int t = 0; t < 4; t++) {
        int idx = tid + t * 256;           // 1024 uint4 per array
        int r = idx >> 3, c8 = idx & 7;
        int o = r * PCH + c8 * 8;
        size_t gq = qbase + (size_t)r * DD + c8 * 8;
        *(uint4*)&sb[QHI_OFF + o] = *(const uint4*)&g_qh[gq];
        *(uint4*)&sb[QLO_OFF + o] = *(const uint4*)&g_ql[gq];
    }
#pragma unroll
    for (int t = 0; t < 2; t++) {
        int idx = tid + t * 256;           // 512 uint4
        int r = idx >> 3, c8 = idx & 7;
        *(uint4*)&sb[KHI_OFF + r * PCH + c8 * 8] =
            *(const uint4*)&g_kh[kbase + (size_t)r * DD + c8 * 8];
    }
    __syncthreads();

    float4 acc[8];
#pragma unroll
    for (int jf = 0; jf < 8; jf++) acc[jf] = make_float4(0.f, 0.f, 0.f, 0.f);

    const int a_row = w * 16 + (lane & 15);
    const int a_kof = (lane >> 4) << 3;
    const int b_row = ((lane >> 4) << 3) + (lane & 7);
    const int b_kof = ((lane >> 3) & 1) << 3;

#pragma unroll
    for (int ks = 0; ks < 4; ks++) {
        const int k0 = ks * 16;
        uint32_t ah[4], al[4];
        ldmatrix_x4(ah[0], ah[1], ah[2], ah[3],
                    smem_u32(&sb[QHI_OFF + a_row * PCH + k0 + a_kof]));
        ldmatrix_x4(al[0], al[1], al[2], al[3],
                    smem_u32(&sb[QLO_OFF + a_row * PCH + k0 + a_kof]));
#pragma unroll
        for (int jp = 0; jp < 4; jp++) {
            uint32_t bh0, bh1, bh2, bh3;
            ldmatrix_x4(bh0, bh1, bh2, bh3,
                        smem_u32(&sb[KHI_OFF + (jp * 16 + b_row) * PCH + k0 + b_kof]));
            mma_f16(acc[jp * 2],     ah, bh0, bh1);
            mma_f16(acc[jp * 2],     al, bh0, bh1);
            mma_f16(acc[jp * 2 + 1], ah, bh2, bh3);
            mma_f16(acc[jp * 2 + 1], al, bh2, bh3);
        }
    }

    // ---- epilogue: u = exp(s) (masked -> 0), fp16 store, per-warp row sums ----
    const int qr = lane >> 2, qc = (lane & 3) * 2;
    const int lr0 = w * 16 + qr;
    const int r0g = i0 + lr0;
    const size_t srow0 = ((size_t)(b * NH + n) * LL + r0g) * LL + j0;
    const size_t srow1 = srow0 + (size_t)8 * LL;
    float sum0 = 0.f, sum1 = 0.f;
#pragma unroll
    for (int jf = 0; jf < 8; jf++) {
        const int lj = jf * 8 + qc;
        float4 a = acc[jf];
        unsigned char m0a = Msk[lr0 * 64 + lj],       m0b = Msk[lr0 * 64 + lj + 1];
        unsigned char m1a = Msk[(lr0 + 8) * 64 + lj], m1b = Msk[(lr0 + 8) * 64 + lj + 1];
        float u0x = m0a ? 0.f : __expf(a.x * SCALE);
        float u0y = m0b ? 0.f : __expf(a.y * SCALE);
        float u1x = m1a ? 0.f : __expf(a.z * SCALE);
        float u1y = m1b ? 0.f : __expf(a.w * SCALE);
        *(__half2*)&g_scores[srow0 + lj] = __floats2half2_rn(u0x, u0y);
        *(__half2*)&g_scores[srow1 + lj] = __floats2half2_rn(u1x, u1y);
        sum0 += u0x + u0y;
        sum1 += u1x + u1y;
    }
    sum0 += __shfl_xor_sync(0xffffffffu, sum0, 1);
    sum0 += __shfl_xor_sync(0xffffffffu, sum0, 2);
    sum1 += __shfl_xor_sync(0xffffffffu, sum1, 1);
    sum1 += __shfl_xor_sync(0xffffffffu, sum1, 2);
    if ((lane & 3) == 0) {
        size_t base = (size_t)jt * NROWS + (size_t)(b * NH + n) * LL + r0g;
        g_tl[base] = sum0;
        g_tl[base + 8] = sum1;
    }
}

// ---------------------------------------------------------------------------
// Kernel 2: combine tile sums -> g_c = 1/L.
// ---------------------------------------------------------------------------
__global__ __launch_bounds__(256) void k_comb()
{
    const int r = blockIdx.x * 256 + threadIdx.x;
    float L = 0.f;
#pragma unroll
    for (int t = 0; t < NTJ; t++) L += g_tl[(size_t)t * NROWS + r];
    const int i = r & (LL - 1);
    const int n = (r >> 11) & (NH - 1);
    const int b = r >> 15;
    g_c[((size_t)(b * LL + i)) * NH + n] = 1.f / L;
}

// ---------------------------------------------------------------------------
// Kernel 3: attn output. 512 threads (32 warps/SM @ 2 CTA).
// p = u * c, transpose [b,n,i,j](fp16) -> [b,i,j,n](f32). 32i x 32j x 16n tile.
// ---------------------------------------------------------------------------
#define RS 545
__global__ __launch_bounds__(512, 2) void k_attn(float* __restrict__ attn)
{
    extern __shared__ float S[];       // 32*RS floats
    __shared__ float Cs[512];          // [32 ii][16 n]
    const int b = blockIdx.z, i0 = blockIdx.y * 32, j0 = blockIdx.x * 32;
    const int tid = threadIdx.x;

    Cs[tid] = g_c[(size_t)(b * LL + i0) * NH + tid];
    __syncthreads();

#pragma unroll
    for (int kk = 0; kk < 4; kk++) {
        int idx = tid + kk * 512;          // 2048 uint4 (8 halves each)
        int c8 = idx & 3, ii = (idx >> 2) & 31, n = idx >> 7;
        uint4 raw = *(const uint4*)&g_scores[
            (((size_t)(b * NH + n)) * LL + i0 + ii) * LL + j0 + c8 * 8];
        const __half2* h2 = (const __half2*)&raw;
        float c = Cs[ii * 16 + n];
        int sbase = ii * 17 + n;
#pragma unroll
        for (int t = 0; t < 4; t++) {
            float2 f = __half22float2(h2[t]);
            int jl = c8 * 8 + t * 2;
            S[jl * RS + sbase] = f.x * c;
            S[(jl + 1) * RS + sbase] = f.y * c;
        }
    }
    __syncthreads();

#pragma unroll
    for (int kk = 0; kk < 8; kk++) {
        int idx = tid + kk * 512;          // 4096 float4
        int n4 = (idx & 3) * 4, jj = (idx >> 2) & 31, ii = idx >> 7;
        const float* s = &S[jj * RS + ii * 17 + n4];
        float4 v = make_float4(s[0], s[1], s[2], s[3]);
        *(float4*)&attn[(((size_t)(b * LL + i0 + ii)) * LL + j0 + jj) * NH + n4] = v;
    }
}

// ---------------------------------------------------------------------------
// Kernel 4: tensor PV, cp.async double-buffered, fp16 V (no lo term).
// CTA = (b,n) x 128 i. 8 warps, warp = 16 i x 64 d. ctx = c * (P_f16 @ Vh).
// ---------------------------------------------------------------------------
#define PVB_L 0
#define VVH_L (128 * PCH)
#define ST_ELEMS (128 * PCH + 64 * PCH)         // 13824 halves / stage
#define SMEM4_BYTES (2 * ST_ELEMS * 2)          // 55296 B

__global__ __launch_bounds__(256, 3) void k_pvt(float* __restrict__ ctx)
{
    extern __shared__ __half pb[];

    const int bn = blockIdx.x;           // b*16+n
    const int b = bn >> 4, n = bn & 15;
    const int i0 = blockIdx.y * 128;
    const int tid = threadIdx.x, w = tid >> 5, lane = tid & 31;

    float4 acc[8];
#pragma unroll
    for (int g = 0; g < 8; g++) acc[g] = make_float4(0.f, 0.f, 0.f, 0.f);

    const size_t ubase = ((size_t)bn * LL + i0) * LL;
    const size_t vbase = (size_t)bn * LL * DD;
    const uint32_t pb0 = smem_u32(pb);

    const int a_row = w * 16 + (lane & 15);
    const int a_kof = (lane >> 4) << 3;
    const int v_rof = ((lane >> 3) & 1) * 8 + (lane & 7);
    const int v_cof = (lane >> 4) * 8;

    // async stage loader: V [64 j][64 d] + u [128 i][64 j]
    auto issue = [&](int jt, int stage) {
        const uint32_t dst = pb0 + stage * (ST_ELEMS * 2);
        const int j0 = jt * 64;
        {
            int idx = tid;                 // 512 lines for V (2 per thread)
            int r = idx >> 3, c8 = idx & 7;
            cp_async16(dst + (VVH_L + r * PCH + c8 * 8) * 2,
                       &g_vh[vbase + (size_t)(j0 + r) * DD + c8 * 8]);
            idx = tid + 256;
            r = idx >> 3; c8 = idx & 7;
            cp_async16(dst + (VVH_L + r * PCH + c8 * 8) * 2,
                       &g_vh[vbase + (size_t)(j0 + r) * DD + c8 * 8]);
        }
#pragma unroll
        for (int t = 0; t < 4; t++) {
            int idx = tid + t * 256;       // 1024 lines for u
            int row = idx >> 3, c8 = idx & 7;
            cp_async16(dst + (PVB_L + row * PCH + c8 * 8) * 2,
                       &g_scores[ubase + (size_t)row * LL + j0 + c8 * 8]);
        }
        CP_COMMIT();
    };

    issue(0, 0);

    for (int jt = 0; jt < NTJ; jt++) {
        const int cur = jt & 1;
        if (jt + 1 < NTJ) {
            issue(jt + 1, cur ^ 1);
            CP_WAIT(1);
        } else {
            CP_WAIT(0);
        }
        __syncthreads();

        const __half* buf = pb + cur * ST_ELEMS;
#pragma unroll
        for (int ks = 0; ks < 4; ks++) {
            const int k0 = ks * 16;
            uint32_t ah[4];
            ldmatrix_x4(ah[0], ah[1], ah[2], ah[3],
                        smem_u32(&buf[PVB_L + a_row * PCH + k0 + a_kof]));
#pragma unroll
            for (int ng = 0; ng < 4; ng++) {
                uint32_t bh0, bh1, bh2, bh3;
                const int voff = (k0 + v_rof) * PCH + ng * 16 + v_cof;
                ldmatrix_x4_t(bh0, bh1, bh2, bh3, smem_u32(&buf[VVH_L + voff]));
                mma_f16(acc[ng * 2],     ah, bh0, bh1);
                mma_f16(acc[ng * 2 + 1], ah, bh2, bh3);
            }
        }
        __syncthreads();
    }

    const int r = w * 16 + (lane >> 2);
    const float c0 = g_c[((size_t)(b * LL + i0 + r)) * NH + n];
    const float c1 = g_c[((size_t)(b * LL + i0 + r + 8)) * NH + n];
#pragma unroll
    for (int ng = 0; ng < 8; ng++) {
        int colb = ng * 8 + (lane & 3) * 2;
        size_t g0 = (((size_t)(b * LL + i0 + r)) * NH + n) * DD + colb;
        size_t g1 = (((size_t)(b * LL + i0 + r + 8)) * NH + n) * DD + colb;
        *(float2*)&ctx[g0] = make_float2(acc[ng].x * c0, acc[ng].y * c0);
        *(float2*)&ctx[g1] = make_float2(acc[ng].z * c1, acc[ng].w * c1);
    }
}

// ---------------------------------------------------------------------------
extern "C" void kernel_launch(void* const* d_in, const int* in_sizes, int n_in,
                              void* d_out, int out_size)
{
    const float* q = (const float*)d_in[0];
    const float* k = (const float*)d_in[1];
    const float* v = (const float*)d_in[2];
    const int* mask = (const int*)d_in[3];

    float* ctx  = (float*)d_out;
    float* attn = (float*)d_out + (size_t)BB * LL * NH * DD;

    const int smem_attn = 32 * RS * 4;          // 69760 B
    cudaFuncSetAttribute(k_scores, cudaFuncAttributeMaxDynamicSharedMemorySize, SMEM1_BYTES);
    cudaFuncSetAttribute(k_attn,   cudaFuncAttributeMaxDynamicSharedMemorySize, smem_attn);
    cudaFuncSetAttribute(k_pvt,    cudaFuncAttributeMaxDynamicSharedMemorySize, SMEM4_BYTES);

    k_split<<<(BB * NH * LL * 32) / 256, 256>>>(q, k, v);

    dim3 g1(BB * NH, LL / TJ, LL / TI);
    k_scores<<<g1, 256, SMEM1_BYTES>>>(mask);

    k_comb<<<NROWS / 256, 256>>>();

    dim3 ga(LL / 32, LL / 32, BB);
    k_attn<<<ga, 512, smem_attn>>>(attn);

    dim3 gp(BB * NH, LL / 128);
    k_pvt<<<gp, 256, SMEM4_BYTES>>>(ctx);
}